// round 1
// baseline (speedup 1.0000x reference)
#include <cuda_runtime.h>

#define D_MODEL 1024
#define N_HEADS 16
#define DKH     64
#define B_      4
#define T_      2048
#define M_TOT   (B_ * T_)        // 8192
#define N_QKV   (3 * D_MODEL)    // 3072

// ---------------- scratch (device globals; no allocation allowed) ----------
__device__ float g_q[(size_t)B_ * N_HEADS * T_ * DKH];     // 32 MB
__device__ float g_k[(size_t)B_ * N_HEADS * T_ * DKH];     // 32 MB
__device__ float g_v[(size_t)B_ * N_HEADS * T_ * DKH];     // 32 MB
__device__ float g_attn[(size_t)M_TOT * D_MODEL];          // 32 MB

// ---------------------------------------------------------------------------
// Tiled SGEMM: C[M,N] = A[M,K] @ B[K,N], 128x128x16 tile, 8x8 per-thread.
// MODE 0: A = x param, epilogue scatters into g_q/g_k/g_v ((B,H,T,dk) layout)
// MODE 1: A = g_attn (internal), plain epilogue to C param
// All dims divide tiles exactly for this problem: no bounds checks.
// ---------------------------------------------------------------------------
template<int MODE>
__global__ __launch_bounds__(256)
void sgemm_kernel(const float* __restrict__ Ap, const float* __restrict__ Bp,
                  float* __restrict__ Cp, int N, int K)
{
    const int BM = 128, BN = 128, BK = 16;
    __shared__ float As[BK][BM + 1];   // transposed A tile, +1 pad
    __shared__ float Bs[BK][BN];

    const float* A = (MODE == 1) ? g_attn : Ap;

    const int tid = threadIdx.x;
    const int ty = tid >> 4;          // 0..15
    const int tx = tid & 15;          // 0..15
    const int row0 = blockIdx.y * BM;
    const int col0 = blockIdx.x * BN;

    float acc[8][8];
    #pragma unroll
    for (int i = 0; i < 8; i++)
        #pragma unroll
        for (int j = 0; j < 8; j++) acc[i][j] = 0.f;

    for (int kt = 0; kt < K; kt += BK) {
        // load A tile (128x16) -> As transposed. 512 float4 total, 2/thread.
        #pragma unroll
        for (int i = 0; i < 2; i++) {
            int f  = tid + i * 256;
            int r  = f >> 2;             // row within tile 0..127
            int c4 = (f & 3) * 4;        // col within tile 0,4,8,12
            float4 a = *(const float4*)(A + (size_t)(row0 + r) * K + kt + c4);
            As[c4 + 0][r] = a.x;
            As[c4 + 1][r] = a.y;
            As[c4 + 2][r] = a.z;
            As[c4 + 3][r] = a.w;
        }
        // load B tile (16x128). 512 float4 total, 2/thread.
        #pragma unroll
        for (int i = 0; i < 2; i++) {
            int f  = tid + i * 256;
            int r  = f >> 5;             // 0..15
            int c4 = (f & 31) * 4;       // 0..124
            *(float4*)(&Bs[r][c4]) =
                *(const float4*)(Bp + (size_t)(kt + r) * N + col0 + c4);
        }
        __syncthreads();

        #pragma unroll
        for (int k = 0; k < BK; k++) {
            float af[8], bf[8];
            #pragma unroll
            for (int i = 0; i < 8; i++) af[i] = As[k][ty * 8 + i];
            #pragma unroll
            for (int j = 0; j < 8; j++) bf[j] = Bs[k][tx * 8 + j];
            #pragma unroll
            for (int i = 0; i < 8; i++)
                #pragma unroll
                for (int j = 0; j < 8; j++)
                    acc[i][j] += af[i] * bf[j];
        }
        __syncthreads();
    }

    if (MODE == 0) {
        // scatter into g_q / g_k / g_v with (B,H,T,dk) layout
        #pragma unroll
        for (int i = 0; i < 8; i++) {
            int gm = row0 + ty * 8 + i;       // 0..8191
            int b  = gm >> 11;                // /2048
            int t  = gm & (T_ - 1);
            #pragma unroll
            for (int j = 0; j < 8; j++) {
                int gn  = col0 + tx * 8 + j;  // 0..3071
                int s   = gn >> 10;           // 0=q 1=k 2=v
                int dmi = gn & (D_MODEL - 1);
                int h   = dmi >> 6;
                int dk  = dmi & (DKH - 1);
                float* dst = (s == 0) ? g_q : (s == 1) ? g_k : g_v;
                dst[(((size_t)(b * N_HEADS + h)) * T_ + t) * DKH + dk] = acc[i][j];
            }
        }
    } else {
        #pragma unroll
        for (int i = 0; i < 8; i++) {
            int gm = row0 + ty * 8 + i;
            #pragma unroll
            for (int j4 = 0; j4 < 2; j4++) {
                float4 v;
                v.x = acc[i][j4 * 4 + 0];
                v.y = acc[i][j4 * 4 + 1];
                v.z = acc[i][j4 * 4 + 2];
                v.w = acc[i][j4 * 4 + 3];
                *(float4*)(Cp + (size_t)gm * N + col0 + tx * 8 + j4 * 4) = v;
            }
        }
    }
}

// ---------------------------------------------------------------------------
// Causal flash attention, fp32. BM=BN=64, d_k=64. 256 threads:
// 4 threads per query row (cg = col group of 16). Online softmax.
// grid = (T/64, B*H)
// ---------------------------------------------------------------------------
#define SM_STRIDE 68   // 64 + 4 pad, float4-aligned, bank-conflict-free

__global__ __launch_bounds__(256)
void attn_kernel()
{
    const int bh  = blockIdx.y;           // 0..63
    const int q0  = blockIdx.x * 64;
    const int tid = threadIdx.x;
    const int r   = tid >> 2;             // query row within tile, 0..63
    const int cg  = tid & 3;              // column group, 0..3 (16 cols each)

    __shared__ float Qs[64 * SM_STRIDE];
    __shared__ float Kt[64 * SM_STRIDE];  // transposed: Kt[d][c]
    __shared__ float Vs[64 * SM_STRIDE];  // Vs[c][d]
    __shared__ float Ps[64 * SM_STRIDE];  // probs

    const float* Qg = g_q + ((size_t)bh * T_ + q0) * DKH;
    const float* Kg = g_k + (size_t)bh * T_ * DKH;
    const float* Vg = g_v + (size_t)bh * T_ * DKH;

    const float SCALE = 0.125f;                    // 1/sqrt(64)
    const float LOG2E = 1.4426950408889634f;

    // load Q tile once, pre-scaled
    #pragma unroll
    for (int i = 0; i < 4; i++) {
        int f = tid + i * 256;            // 0..1023 float4 slots
        int c = f >> 4;                   // row 0..63
        int d = (f & 15) * 4;
        float4 q4 = *(const float4*)(Qg + (size_t)c * DKH + d);
        Qs[c * SM_STRIDE + d + 0] = q4.x * SCALE;
        Qs[c * SM_STRIDE + d + 1] = q4.y * SCALE;
        Qs[c * SM_STRIDE + d + 2] = q4.z * SCALE;
        Qs[c * SM_STRIDE + d + 3] = q4.w * SCALE;
    }

    float o[16];
    #pragma unroll
    for (int j = 0; j < 16; j++) o[j] = 0.f;
    float m = -1e30f, l = 0.f;

    const int ntiles = (q0 >> 6) + 1;     // causal: only tiles with k0 <= q0

    for (int kt_i = 0; kt_i < ntiles; ++kt_i) {
        const int k0 = kt_i * 64;
        __syncthreads();   // smem safe to overwrite (also covers Q-load on iter 0)

        // load K (transposed) and V tiles
        #pragma unroll
        for (int i = 0; i < 4; i++) {
            int f = tid + i * 256;
            int c = f >> 4;
            int d = (f & 15) * 4;
            float4 k4 = *(const float4*)(Kg + (size_t)(k0 + c) * DKH + d);
            Kt[(d + 0) * SM_STRIDE + c] = k4.x;
            Kt[(d + 1) * SM_STRIDE + c] = k4.y;
            Kt[(d + 2) * SM_STRIDE + c] = k4.z;
            Kt[(d + 3) * SM_STRIDE + c] = k4.w;
            float4 v4 = *(const float4*)(Vg + (size_t)(k0 + c) * DKH + d);
            *(float4*)(&Vs[c * SM_STRIDE + d]) = v4;
        }
        __syncthreads();

        // S = Q @ K^T  (this thread: row r, cols cg*16 .. cg*16+15)
        float s[16];
        #pragma unroll
        for (int j = 0; j < 16; j++) s[j] = 0.f;
        #pragma unroll 8
        for (int k = 0; k < 64; k++) {
            float qv = Qs[r * SM_STRIDE + k];
            const float* kp = &Kt[k * SM_STRIDE + cg * 16];
            #pragma unroll
            for (int j4 = 0; j4 < 4; j4++) {
                float4 kv = *(const float4*)(kp + j4 * 4);
                s[j4 * 4 + 0] += qv * kv.x;
                s[j4 * 4 + 1] += qv * kv.y;
                s[j4 * 4 + 2] += qv * kv.z;
                s[j4 * 4 + 3] += qv * kv.w;
            }
        }

        // causal mask (only the diagonal tile is partially masked)
        if (k0 == q0) {
            #pragma unroll
            for (int j = 0; j < 16; j++)
                if (cg * 16 + j > r) s[j] = -1e30f;
        }

        // online softmax
        float mt = s[0];
        #pragma unroll
        for (int j = 1; j < 16; j++) mt = fmaxf(mt, s[j]);
        mt = fmaxf(mt, __shfl_xor_sync(0xffffffff, mt, 1));
        mt = fmaxf(mt, __shfl_xor_sync(0xffffffff, mt, 2));
        float mn    = fmaxf(m, mt);
        float alpha = exp2f((m - mn) * LOG2E);
        float rs = 0.f;
        #pragma unroll
        for (int j = 0; j < 16; j++) {
            float p = exp2f((s[j] - mn) * LOG2E);
            s[j] = p;
            rs  += p;
        }
        rs += __shfl_xor_sync(0xffffffff, rs, 1);
        rs += __shfl_xor_sync(0xffffffff, rs, 2);
        l = l * alpha + rs;
        m = mn;
        #pragma unroll
        for (int j = 0; j < 16; j++) o[j] *= alpha;

        // publish P (within-warp: the 4 writers of row r are same-warp lanes)
        #pragma unroll
        for (int j = 0; j < 16; j++)
            Ps[r * SM_STRIDE + cg * 16 + j] = s[j];
        __syncwarp();

        // O += P @ V  (this thread: row r, d-cols cg*16 .. cg*16+15)
        #pragma unroll 4
        for (int c = 0; c < 64; c++) {
            float p = Ps[r * SM_STRIDE + c];
            const float* vp = &Vs[c * SM_STRIDE + cg * 16];
            #pragma unroll
            for (int j4 = 0; j4 < 4; j4++) {
                float4 vv = *(const float4*)(vp + j4 * 4);
                o[j4 * 4 + 0] += p * vv.x;
                o[j4 * 4 + 1] += p * vv.y;
                o[j4 * 4 + 2] += p * vv.z;
                o[j4 * 4 + 3] += p * vv.w;
            }
        }
    }

    // normalize + write to g_attn in (B,T,D) layout (heads re-interleaved)
    const float inv_l = 1.f / l;
    const int q = q0 + r;
    const int b = bh >> 4;
    const int h = bh & 15;
    float* og = g_attn + ((size_t)(b * T_ + q)) * D_MODEL + h * DKH + cg * 16;
    #pragma unroll
    for (int j4 = 0; j4 < 4; j4++) {
        float4 ov;
        ov.x = o[j4 * 4 + 0] * inv_l;
        ov.y = o[j4 * 4 + 1] * inv_l;
        ov.z = o[j4 * 4 + 2] * inv_l;
        ov.w = o[j4 * 4 + 3] * inv_l;
        *(float4*)(og + j4 * 4) = ov;
    }
}

// ---------------------------------------------------------------------------
extern "C" void kernel_launch(void* const* d_in, const int* in_sizes, int n_in,
                              void* d_out, int out_size)
{
    const float* x     = (const float*)d_in[0];   // (4,2048,1024)
    const float* w_qkv = (const float*)d_in[1];   // (1024,3072)
    const float* w_out = (const float*)d_in[2];   // (1024,1024)
    float* out = (float*)d_out;                   // (4,2048,1024)

    // 1) QKV projection, scatter into (B,H,T,dk) q/k/v buffers
    sgemm_kernel<0><<<dim3(N_QKV / 128, M_TOT / 128), 256>>>(
        x, w_qkv, nullptr, N_QKV, D_MODEL);

    // 2) causal flash attention -> g_attn (B,T,D)
    attn_kernel<<<dim3(T_ / 64, B_ * N_HEADS), 256>>>();

    // 3) output projection -> d_out
    sgemm_kernel<1><<<dim3(D_MODEL / 128, M_TOT / 128), 256>>>(
        nullptr, w_out, out, D_MODEL, D_MODEL);
}

// round 6
// speedup vs baseline: 1.0016x; 1.0016x over previous
#include <cuda_runtime.h>
#include <cuda_bf16.h>
#include <cstdint>

#define D_MODEL 1024
#define N_HEADS 16
#define DKH     64
#define B_      4
#define T_      2048
#define M_TOT   (B_ * T_)        // 8192
#define N_QKV   (3 * D_MODEL)    // 3072
#define GK      1024             // K of both GEMMs

// ---------------- scratch (device globals; no allocation allowed) ----------
__device__ float g_q[(size_t)B_ * N_HEADS * T_ * DKH];     // 32 MB
__device__ float g_k[(size_t)B_ * N_HEADS * T_ * DKH];     // 32 MB
__device__ float g_v[(size_t)B_ * N_HEADS * T_ * DKH];     // 32 MB
__device__ float g_attn[(size_t)M_TOT * D_MODEL];          // 32 MB

// ============================ PTX helpers ==================================
#define MMA_BF16(D, A, b0, b1) \
    asm volatile("mma.sync.aligned.m16n8k16.row.col.f32.bf16.bf16.f32 " \
        "{%0,%1,%2,%3}, {%4,%5,%6,%7}, {%8,%9}, {%0,%1,%2,%3};" \
        : "+f"((D)[0]), "+f"((D)[1]), "+f"((D)[2]), "+f"((D)[3]) \
        : "r"((A)[0]), "r"((A)[1]), "r"((A)[2]), "r"((A)[3]), "r"(b0), "r"(b1))

__device__ __forceinline__ void bf16_split(float x, unsigned short& h, unsigned short& l)
{
    __nv_bfloat16 hb = __float2bfloat16(x);
    h = __bfloat16_as_ushort(hb);
    l = __bfloat16_as_ushort(__float2bfloat16(x - __bfloat162float(hb)));
}

// ===================== bf16 HMMA GEMM (mma.sync) ===========================
// C[M,N] = A[M,K](fp32) @ B[K,N](fp32), with in-register 2-term bf16 split:
//   C = AhBh + AhBl + AlBh   (fp32 accumulate)
// CTA tile 128x128, 8 warps (2x4), warp tile 64x32, BK=32.
// A kept row-major [m][k] in smem; B transposed to [n][k] during smem store.
// Fragments via direct 32-bit LDS per the PTX m16n8k16 fragment tables.
// MODE 0: scatter epilogue into g_q/g_k/g_v. MODE 1: plain store to C.
#define BKS      32
#define ASTRIDE  40     // bf16 elements per smem row (32 data + 8 pad)

template<int MODE>
__global__ __launch_bounds__(256)
void gemm_mma(const float* __restrict__ Ap, const float* __restrict__ Bp,
              float* __restrict__ Cp, int N)
{
    __shared__ __align__(16) __nv_bfloat16 sAh[128][ASTRIDE];
    __shared__ __align__(16) __nv_bfloat16 sAl[128][ASTRIDE];
    __shared__ __align__(16) __nv_bfloat16 sBh[128][ASTRIDE];  // [n][k]
    __shared__ __align__(16) __nv_bfloat16 sBl[128][ASTRIDE];

    const int tid  = threadIdx.x;
    const int wid  = tid >> 5;
    const int lane = tid & 31;
    const int wm   = wid & 1;       // warp row (2)
    const int wn   = wid >> 1;      // warp col (4)
    const int gid  = lane >> 2;     // group id 0..7
    const int tig  = lane & 3;      // thread in group 0..3
    const int row0 = blockIdx.y * 128;
    const int col0 = blockIdx.x * 128;

    const float* A = (MODE == 1) ? g_attn : Ap;

    float d[4][4][4];
    #pragma unroll
    for (int i = 0; i < 4; i++)
        #pragma unroll
        for (int j = 0; j < 4; j++)
            #pragma unroll
            for (int e = 0; e < 4; e++) d[i][j][e] = 0.f;

    for (int kt = 0; kt < GK / BKS; kt++) {
        // ---- global loads (fp32, R1-style float4) ----
        float4 av[4], bv[4];
        #pragma unroll
        for (int i = 0; i < 4; i++) {
            const int idx = tid + i * 256;          // 0..1023
            const int ar  = idx >> 3;               // A row 0..127
            const int ac  = (idx & 7) * 4;          // A col 0..28
            av[i] = *(const float4*)(A + (size_t)(row0 + ar) * GK + kt * BKS + ac);
            const int bk  = idx >> 5;               // B k-row 0..31
            const int bn  = (idx & 31) * 4;         // B n-col 0..124
            bv[i] = *(const float4*)(Bp + (size_t)(kt * BKS + bk) * N + col0 + bn);
        }
        __syncthreads();   // previous stage's compute done before overwrite

        // ---- split + store to smem (A row-major, B transposed to [n][k]) ----
        #pragma unroll
        for (int i = 0; i < 4; i++) {
            const int idx = tid + i * 256;
            const int ar  = idx >> 3;
            const int ac  = (idx & 7) * 4;
            ushort4 h4, l4;
            bf16_split(av[i].x, h4.x, l4.x);
            bf16_split(av[i].y, h4.y, l4.y);
            bf16_split(av[i].z, h4.z, l4.z);
            bf16_split(av[i].w, h4.w, l4.w);
            *(ushort4*)&sAh[ar][ac] = h4;
            *(ushort4*)&sAl[ar][ac] = l4;

            const int bk = idx >> 5;
            const int bn = (idx & 31) * 4;
            const float xs[4] = {bv[i].x, bv[i].y, bv[i].z, bv[i].w};
            #pragma unroll
            for (int j = 0; j < 4; j++) {
                unsigned short hh, ll;
                bf16_split(xs[j], hh, ll);
                sBh[bn + j][bk] = __ushort_as_bfloat16(hh);
                sBl[bn + j][bk] = __ushort_as_bfloat16(ll);
            }
        }
        __syncthreads();

        // ---- compute ----
        #pragma unroll
        for (int kk = 0; kk < 2; kk++) {
            const int kb = kk * 16 + tig * 2;   // this thread's k pair base

            uint32_t Afh[4][4], Afl[4][4];
            #pragma unroll
            for (int mi = 0; mi < 4; mi++) {
                const int r0 = wm * 64 + mi * 16 + gid;
                Afh[mi][0] = *(const uint32_t*)&sAh[r0][kb];
                Afh[mi][1] = *(const uint32_t*)&sAh[r0 + 8][kb];
                Afh[mi][2] = *(const uint32_t*)&sAh[r0][kb + 8];
                Afh[mi][3] = *(const uint32_t*)&sAh[r0 + 8][kb + 8];
                Afl[mi][0] = *(const uint32_t*)&sAl[r0][kb];
                Afl[mi][1] = *(const uint32_t*)&sAl[r0 + 8][kb];
                Afl[mi][2] = *(const uint32_t*)&sAl[r0][kb + 8];
                Afl[mi][3] = *(const uint32_t*)&sAl[r0 + 8][kb + 8];
            }
            uint32_t Bfh[4][2], Bfl[4][2];
            #pragma unroll
            for (int ng = 0; ng < 4; ng++) {
                const int nr = wn * 32 + ng * 8 + gid;
                Bfh[ng][0] = *(const uint32_t*)&sBh[nr][kb];
                Bfh[ng][1] = *(const uint32_t*)&sBh[nr][kb + 8];
                Bfl[ng][0] = *(const uint32_t*)&sBl[nr][kb];
                Bfl[ng][1] = *(const uint32_t*)&sBl[nr][kb + 8];
            }
            #pragma unroll
            for (int mi = 0; mi < 4; mi++) {
                #pragma unroll
                for (int ng = 0; ng < 4; ng++) {
                    MMA_BF16(d[mi][ng], Afh[mi], Bfh[ng][0], Bfh[ng][1]);
                    MMA_BF16(d[mi][ng], Afh[mi], Bfl[ng][0], Bfl[ng][1]);
                    MMA_BF16(d[mi][ng], Afl[mi], Bfh[ng][0], Bfh[ng][1]);
                }
            }
        }
    }

    // ---------------- epilogue ----------------
    // c0,c1:(m=gid, n=tig*2+{0,1})  c2,c3:(m=gid+8, same n)
    #pragma unroll
    for (int mi = 0; mi < 4; mi++) {
        #pragma unroll
        for (int ng = 0; ng < 4; ng++) {
            const int n = col0 + wn * 32 + ng * 8 + tig * 2;
            #pragma unroll
            for (int h = 0; h < 2; h++) {
                const int m = row0 + wm * 64 + mi * 16 + gid + h * 8;
                float2 v;
                v.x = d[mi][ng][h * 2 + 0];
                v.y = d[mi][ng][h * 2 + 1];
                if (MODE == 0) {
                    int b = m >> 11, t = m & (T_ - 1);
                    int sidx = n >> 10;
                    int dmi  = n & (D_MODEL - 1);
                    int hh = dmi >> 6, dk = dmi & (DKH - 1);
                    float* base = (sidx == 0) ? g_q : (sidx == 1) ? g_k : g_v;
                    *(float2*)(base + (((size_t)((b << 4) + hh)) * T_ + t) * DKH + dk) = v;
                } else {
                    *(float2*)(Cp + (size_t)m * N + n) = v;
                }
            }
        }
    }
}

// ---------------------------------------------------------------------------
// Causal flash attention, fp32 (unchanged from R1, proven). BM=BN=64, d_k=64.
// ---------------------------------------------------------------------------
#define SM_STRIDE 68

__global__ __launch_bounds__(256)
void attn_kernel()
{
    const int bh  = blockIdx.y;
    const int q0  = blockIdx.x * 64;
    const int tid = threadIdx.x;
    const int r   = tid >> 2;
    const int cg  = tid & 3;

    __shared__ float Qs[64 * SM_STRIDE];
    __shared__ float Kt[64 * SM_STRIDE];
    __shared__ float Vs[64 * SM_STRIDE];
    __shared__ float Ps[64 * SM_STRIDE];

    const float* Qg = g_q + ((size_t)bh * T_ + q0) * DKH;
    const float* Kg = g_k + (size_t)bh * T_ * DKH;
    const float* Vg = g_v + (size_t)bh * T_ * DKH;

    const float SCALE = 0.125f;
    const float LOG2E = 1.4426950408889634f;

    #pragma unroll
    for (int i = 0; i < 4; i++) {
        int f = tid + i * 256;
        int c = f >> 4;
        int d = (f & 15) * 4;
        float4 q4 = *(const float4*)(Qg + (size_t)c * DKH + d);
        Qs[c * SM_STRIDE + d + 0] = q4.x * SCALE;
        Qs[c * SM_STRIDE + d + 1] = q4.y * SCALE;
        Qs[c * SM_STRIDE + d + 2] = q4.z * SCALE;
        Qs[c * SM_STRIDE + d + 3] = q4.w * SCALE;
    }

    float o[16];
    #pragma unroll
    for (int j = 0; j < 16; j++) o[j] = 0.f;
    float m = -1e30f, l = 0.f;

    const int ntiles = (q0 >> 6) + 1;

    for (int kt_i = 0; kt_i < ntiles; ++kt_i) {
        const int k0 = kt_i * 64;
        __syncthreads();

        #pragma unroll
        for (int i = 0; i < 4; i++) {
            int f = tid + i * 256;
            int c = f >> 4;
            int d = (f & 15) * 4;
            float4 k4 = *(const float4*)(Kg + (size_t)(k0 + c) * DKH + d);
            Kt[(d + 0) * SM_STRIDE + c] = k4.x;
            Kt[(d + 1) * SM_STRIDE + c] = k4.y;
            Kt[(d + 2) * SM_STRIDE + c] = k4.z;
            Kt[(d + 3) * SM_STRIDE + c] = k4.w;
            float4 v4 = *(const float4*)(Vg + (size_t)(k0 + c) * DKH + d);
            *(float4*)(&Vs[c * SM_STRIDE + d]) = v4;
        }
        __syncthreads();

        float s[16];
        #pragma unroll
        for (int j = 0; j < 16; j++) s[j] = 0.f;
        #pragma unroll 8
        for (int k = 0; k < 64; k++) {
            float qv = Qs[r * SM_STRIDE + k];
            const float* kp = &Kt[k * SM_STRIDE + cg * 16];
            #pragma unroll
            for (int j4 = 0; j4 < 4; j4++) {
                float4 kv = *(const float4*)(kp + j4 * 4);
                s[j4 * 4 + 0] += qv * kv.x;
                s[j4 * 4 + 1] += qv * kv.y;
                s[j4 * 4 + 2] += qv * kv.z;
                s[j4 * 4 + 3] += qv * kv.w;
            }
        }

        if (k0 == q0) {
            #pragma unroll
            for (int j = 0; j < 16; j++)
                if (cg * 16 + j > r) s[j] = -1e30f;
        }

        float mt = s[0];
        #pragma unroll
        for (int j = 1; j < 16; j++) mt = fmaxf(mt, s[j]);
        mt = fmaxf(mt, __shfl_xor_sync(0xffffffff, mt, 1));
        mt = fmaxf(mt, __shfl_xor_sync(0xffffffff, mt, 2));
        float mn    = fmaxf(m, mt);
        float alpha = exp2f((m - mn) * LOG2E);
        float rs = 0.f;
        #pragma unroll
        for (int j = 0; j < 16; j++) {
            float p = exp2f((s[j] - mn) * LOG2E);
            s[j] = p;
            rs  += p;
        }
        rs += __shfl_xor_sync(0xffffffff, rs, 1);
        rs += __shfl_xor_sync(0xffffffff, rs, 2);
        l = l * alpha + rs;
        m = mn;
        #pragma unroll
        for (int j = 0; j < 16; j++) o[j] *= alpha;

        #pragma unroll
        for (int j = 0; j < 16; j++)
            Ps[r * SM_STRIDE + cg * 16 + j] = s[j];
        __syncwarp();

        #pragma unroll 4
        for (int c = 0; c < 64; c++) {
            float p = Ps[r * SM_STRIDE + c];
            const float* vp = &Vs[c * SM_STRIDE + cg * 16];
            #pragma unroll
            for (int j4 = 0; j4 < 4; j4++) {
                float4 vv = *(const float4*)(vp + j4 * 4);
                o[j4 * 4 + 0] += p * vv.x;
                o[j4 * 4 + 1] += p * vv.y;
                o[j4 * 4 + 2] += p * vv.z;
                o[j4 * 4 + 3] += p * vv.w;
            }
        }
    }

    const float inv_l = 1.f / l;
    const int q = q0 + r;
    const int b = bh >> 4;
    const int h = bh & 15;
    float* og = g_attn + ((size_t)(b * T_ + q)) * D_MODEL + h * DKH + cg * 16;
    #pragma unroll
    for (int j4 = 0; j4 < 4; j4++) {
        float4 ov;
        ov.x = o[j4 * 4 + 0] * inv_l;
        ov.y = o[j4 * 4 + 1] * inv_l;
        ov.z = o[j4 * 4 + 2] * inv_l;
        ov.w = o[j4 * 4 + 3] * inv_l;
        *(float4*)(og + j4 * 4) = ov;
    }
}

// ---------------------------------------------------------------------------
extern "C" void kernel_launch(void* const* d_in, const int* in_sizes, int n_in,
                              void* d_out, int out_size)
{
    const float* x     = (const float*)d_in[0];   // (4,2048,1024)
    const float* w_qkv = (const float*)d_in[1];   // (1024,3072)
    const float* w_out = (const float*)d_in[2];   // (1024,1024)
    float* out = (float*)d_out;                   // (4,2048,1024)

    // 1) QKV projection (HMMA, in-kernel bf16 split), scatter into q/k/v
    gemm_mma<0><<<dim3(N_QKV / 128, M_TOT / 128), 256>>>(
        x, w_qkv, nullptr, N_QKV);

    // 2) causal flash attention -> g_attn (B,T,D)
    attn_kernel<<<dim3(T_ / 64, B_ * N_HEADS), 256>>>();

    // 3) output projection (HMMA, in-kernel bf16 split) -> d_out
    gemm_mma<1><<<dim3(D_MODEL / 128, M_TOT / 128), 256>>>(
        nullptr, w_out, out, D_MODEL);
}

// round 7
// speedup vs baseline: 1.0078x; 1.0063x over previous
#include <cuda_runtime.h>
#include <cuda_bf16.h>
#include <cstdint>

#define D_MODEL 1024
#define N_HEADS 16
#define DKH     64
#define B_      4
#define T_      2048
#define M_TOT   (B_ * T_)        // 8192
#define N_QKV   (3 * D_MODEL)    // 3072
#define GK      1024             // K of both GEMMs

// ---------------- scratch (device globals; no allocation allowed) ----------
__device__ float g_q[(size_t)B_ * N_HEADS * T_ * DKH];     // 32 MB
__device__ float g_k[(size_t)B_ * N_HEADS * T_ * DKH];     // 32 MB
__device__ float g_v[(size_t)B_ * N_HEADS * T_ * DKH];     // 32 MB
__device__ float g_attn[(size_t)M_TOT * D_MODEL];          // 32 MB

// ============================ PTX helpers ==================================
#define MMA_BF16(D, A, b0, b1) \
    asm volatile("mma.sync.aligned.m16n8k16.row.col.f32.bf16.bf16.f32 " \
        "{%0,%1,%2,%3}, {%4,%5,%6,%7}, {%8,%9}, {%0,%1,%2,%3};" \
        : "+f"((D)[0]), "+f"((D)[1]), "+f"((D)[2]), "+f"((D)[3]) \
        : "r"((A)[0]), "r"((A)[1]), "r"((A)[2]), "r"((A)[3]), "r"(b0), "r"(b1))

__device__ __forceinline__ void bf16_split(float x, unsigned short& h, unsigned short& l)
{
    __nv_bfloat16 hb = __float2bfloat16(x);
    h = __bfloat16_as_ushort(hb);
    l = __bfloat16_as_ushort(__float2bfloat16(x - __bfloat162float(hb)));
}

// ===================== bf16 HMMA GEMM (mma.sync) ===========================
// C[M,N] = A[M,K](fp32) @ B[K,N](fp32), with in-register 2-term bf16 split:
//   C = AhBh + AhBl + AlBh   (fp32 accumulate)
// CTA tile 128x128, 8 warps (2x4), warp tile 64x32, BK=32.
// A kept row-major [m][k] in smem; B transposed to [n][k] during smem store.
// Fragments via direct 32-bit LDS per the PTX m16n8k16 fragment tables.
// MODE 0: scatter epilogue into g_q/g_k/g_v. MODE 1: plain store to C.
#define BKS      32
#define ASTRIDE  40     // bf16 elements per smem row (32 data + 8 pad)

template<int MODE>
__global__ __launch_bounds__(256)
void gemm_mma(const float* __restrict__ Ap, const float* __restrict__ Bp,
              float* __restrict__ Cp, int N)
{
    __shared__ __align__(16) __nv_bfloat16 sAh[128][ASTRIDE];
    __shared__ __align__(16) __nv_bfloat16 sAl[128][ASTRIDE];
    __shared__ __align__(16) __nv_bfloat16 sBh[128][ASTRIDE];  // [n][k]
    __shared__ __align__(16) __nv_bfloat16 sBl[128][ASTRIDE];

    const int tid  = threadIdx.x;
    const int wid  = tid >> 5;
    const int lane = tid & 31;
    const int wm   = wid & 1;       // warp row (2)
    const int wn   = wid >> 1;      // warp col (4)
    const int gid  = lane >> 2;     // group id 0..7
    const int tig  = lane & 3;      // thread in group 0..3
    const int row0 = blockIdx.y * 128;
    const int col0 = blockIdx.x * 128;

    const float* A = (MODE == 1) ? g_attn : Ap;

    float d[4][4][4];
    #pragma unroll
    for (int i = 0; i < 4; i++)
        #pragma unroll
        for (int j = 0; j < 4; j++)
            #pragma unroll
            for (int e = 0; e < 4; e++) d[i][j][e] = 0.f;

    for (int kt = 0; kt < GK / BKS; kt++) {
        // ---- global loads (fp32, R1-style float4) ----
        float4 av[4], bv[4];
        #pragma unroll
        for (int i = 0; i < 4; i++) {
            const int idx = tid + i * 256;          // 0..1023
            const int ar  = idx >> 3;               // A row 0..127
            const int ac  = (idx & 7) * 4;          // A col 0..28
            av[i] = *(const float4*)(A + (size_t)(row0 + ar) * GK + kt * BKS + ac);
            const int bk  = idx >> 5;               // B k-row 0..31
            const int bn  = (idx & 31) * 4;         // B n-col 0..124
            bv[i] = *(const float4*)(Bp + (size_t)(kt * BKS + bk) * N + col0 + bn);
        }
        __syncthreads();   // previous stage's compute done before overwrite

        // ---- split + store to smem (A row-major, B transposed to [n][k]) ----
        #pragma unroll
        for (int i = 0; i < 4; i++) {
            const int idx = tid + i * 256;
            const int ar  = idx >> 3;
            const int ac  = (idx & 7) * 4;
            ushort4 h4, l4;
            bf16_split(av[i].x, h4.x, l4.x);
            bf16_split(av[i].y, h4.y, l4.y);
            bf16_split(av[i].z, h4.z, l4.z);
            bf16_split(av[i].w, h4.w, l4.w);
            *(ushort4*)&sAh[ar][ac] = h4;
            *(ushort4*)&sAl[ar][ac] = l4;

            const int bk = idx >> 5;
            const int bn = (idx & 31) * 4;
            const float xs[4] = {bv[i].x, bv[i].y, bv[i].z, bv[i].w};
            #pragma unroll
            for (int j = 0; j < 4; j++) {
                unsigned short hh, ll;
                bf16_split(xs[j], hh, ll);
                sBh[bn + j][bk] = __ushort_as_bfloat16(hh);
                sBl[bn + j][bk] = __ushort_as_bfloat16(ll);
            }
        }
        __syncthreads();

        // ---- compute ----
        #pragma unroll
        for (int kk = 0; kk < 2; kk++) {
            const int kb = kk * 16 + tig * 2;   // this thread's k pair base

            uint32_t Afh[4][4], Afl[4][4];
            #pragma unroll
            for (int mi = 0; mi < 4; mi++) {
                const int r0 = wm * 64 + mi * 16 + gid;
                Afh[mi][0] = *(const uint32_t*)&sAh[r0][kb];
                Afh[mi][1] = *(const uint32_t*)&sAh[r0 + 8][kb];
                Afh[mi][2] = *(const uint32_t*)&sAh[r0][kb + 8];
                Afh[mi][3] = *(const uint32_t*)&sAh[r0 + 8][kb + 8];
                Afl[mi][0] = *(const uint32_t*)&sAl[r0][kb];
                Afl[mi][1] = *(const uint32_t*)&sAl[r0 + 8][kb];
                Afl[mi][2] = *(const uint32_t*)&sAl[r0][kb + 8];
                Afl[mi][3] = *(const uint32_t*)&sAl[r0 + 8][kb + 8];
            }
            uint32_t Bfh[4][2], Bfl[4][2];
            #pragma unroll
            for (int ng = 0; ng < 4; ng++) {
                const int nr = wn * 32 + ng * 8 + gid;
                Bfh[ng][0] = *(const uint32_t*)&sBh[nr][kb];
                Bfh[ng][1] = *(const uint32_t*)&sBh[nr][kb + 8];
                Bfl[ng][0] = *(const uint32_t*)&sBl[nr][kb];
                Bfl[ng][1] = *(const uint32_t*)&sBl[nr][kb + 8];
            }
            #pragma unroll
            for (int mi = 0; mi < 4; mi++) {
                #pragma unroll
                for (int ng = 0; ng < 4; ng++) {
                    MMA_BF16(d[mi][ng], Afh[mi], Bfh[ng][0], Bfh[ng][1]);
                    MMA_BF16(d[mi][ng], Afh[mi], Bfl[ng][0], Bfl[ng][1]);
                    MMA_BF16(d[mi][ng], Afl[mi], Bfh[ng][0], Bfh[ng][1]);
                }
            }
        }
    }

    // ---------------- epilogue ----------------
    // c0,c1:(m=gid, n=tig*2+{0,1})  c2,c3:(m=gid+8, same n)
    #pragma unroll
    for (int mi = 0; mi < 4; mi++) {
        #pragma unroll
        for (int ng = 0; ng < 4; ng++) {
            const int n = col0 + wn * 32 + ng * 8 + tig * 2;
            #pragma unroll
            for (int h = 0; h < 2; h++) {
                const int m = row0 + wm * 64 + mi * 16 + gid + h * 8;
                float2 v;
                v.x = d[mi][ng][h * 2 + 0];
                v.y = d[mi][ng][h * 2 + 1];
                if (MODE == 0) {
                    int b = m >> 11, t = m & (T_ - 1);
                    int sidx = n >> 10;
                    int dmi  = n & (D_MODEL - 1);
                    int hh = dmi >> 6, dk = dmi & (DKH - 1);
                    float* base = (sidx == 0) ? g_q : (sidx == 1) ? g_k : g_v;
                    *(float2*)(base + (((size_t)((b << 4) + hh)) * T_ + t) * DKH + dk) = v;
                } else {
                    *(float2*)(Cp + (size_t)m * N + n) = v;
                }
            }
        }
    }
}

// ---------------------------------------------------------------------------
// Causal flash attention, fp32 (unchanged from R1, proven). BM=BN=64, d_k=64.
// ---------------------------------------------------------------------------
#define SM_STRIDE 68

__global__ __launch_bounds__(256)
void attn_kernel()
{
    const int bh  = blockIdx.y;
    const int q0  = blockIdx.x * 64;
    const int tid = threadIdx.x;
    const int r   = tid >> 2;
    const int cg  = tid & 3;

    __shared__ float Qs[64 * SM_STRIDE];
    __shared__ float Kt[64 * SM_STRIDE];
    __shared__ float Vs[64 * SM_STRIDE];
    __shared__ float Ps[64 * SM_STRIDE];

    const float* Qg = g_q + ((size_t)bh * T_ + q0) * DKH;
    const float* Kg = g_k + (size_t)bh * T_ * DKH;
    const float* Vg = g_v + (size_t)bh * T_ * DKH;

    const float SCALE = 0.125f;
    const float LOG2E = 1.4426950408889634f;

    #pragma unroll
    for (int i = 0; i < 4; i++) {
        int f = tid + i * 256;
        int c = f >> 4;
        int d = (f & 15) * 4;
        float4 q4 = *(const float4*)(Qg + (size_t)c * DKH + d);
        Qs[c * SM_STRIDE + d + 0] = q4.x * SCALE;
        Qs[c * SM_STRIDE + d + 1] = q4.y * SCALE;
        Qs[c * SM_STRIDE + d + 2] = q4.z * SCALE;
        Qs[c * SM_STRIDE + d + 3] = q4.w * SCALE;
    }

    float o[16];
    #pragma unroll
    for (int j = 0; j < 16; j++) o[j] = 0.f;
    float m = -1e30f, l = 0.f;

    const int ntiles = (q0 >> 6) + 1;

    for (int kt_i = 0; kt_i < ntiles; ++kt_i) {
        const int k0 = kt_i * 64;
        __syncthreads();

        #pragma unroll
        for (int i = 0; i < 4; i++) {
            int f = tid + i * 256;
            int c = f >> 4;
            int d = (f & 15) * 4;
            float4 k4 = *(const float4*)(Kg + (size_t)(k0 + c) * DKH + d);
            Kt[(d + 0) * SM_STRIDE + c] = k4.x;
            Kt[(d + 1) * SM_STRIDE + c] = k4.y;
            Kt[(d + 2) * SM_STRIDE + c] = k4.z;
            Kt[(d + 3) * SM_STRIDE + c] = k4.w;
            float4 v4 = *(const float4*)(Vg + (size_t)(k0 + c) * DKH + d);
            *(float4*)(&Vs[c * SM_STRIDE + d]) = v4;
        }
        __syncthreads();

        float s[16];
        #pragma unroll
        for (int j = 0; j < 16; j++) s[j] = 0.f;
        #pragma unroll 8
        for (int k = 0; k < 64; k++) {
            float qv = Qs[r * SM_STRIDE + k];
            const float* kp = &Kt[k * SM_STRIDE + cg * 16];
            #pragma unroll
            for (int j4 = 0; j4 < 4; j4++) {
                float4 kv = *(const float4*)(kp + j4 * 4);
                s[j4 * 4 + 0] += qv * kv.x;
                s[j4 * 4 + 1] += qv * kv.y;
                s[j4 * 4 + 2] += qv * kv.z;
                s[j4 * 4 + 3] += qv * kv.w;
            }
        }

        if (k0 == q0) {
            #pragma unroll
            for (int j = 0; j < 16; j++)
                if (cg * 16 + j > r) s[j] = -1e30f;
        }

        float mt = s[0];
        #pragma unroll
        for (int j = 1; j < 16; j++) mt = fmaxf(mt, s[j]);
        mt = fmaxf(mt, __shfl_xor_sync(0xffffffff, mt, 1));
        mt = fmaxf(mt, __shfl_xor_sync(0xffffffff, mt, 2));
        float mn    = fmaxf(m, mt);
        float alpha = exp2f((m - mn) * LOG2E);
        float rs = 0.f;
        #pragma unroll
        for (int j = 0; j < 16; j++) {
            float p = exp2f((s[j] - mn) * LOG2E);
            s[j] = p;
            rs  += p;
        }
        rs += __shfl_xor_sync(0xffffffff, rs, 1);
        rs += __shfl_xor_sync(0xffffffff, rs, 2);
        l = l * alpha + rs;
        m = mn;
        #pragma unroll
        for (int j = 0; j < 16; j++) o[j] *= alpha;

        #pragma unroll
        for (int j = 0; j < 16; j++)
            Ps[r * SM_STRIDE + cg * 16 + j] = s[j];
        __syncwarp();

        #pragma unroll 4
        for (int c = 0; c < 64; c++) {
            float p = Ps[r * SM_STRIDE + c];
            const float* vp = &Vs[c * SM_STRIDE + cg * 16];
            #pragma unroll
            for (int j4 = 0; j4 < 4; j4++) {
                float4 vv = *(const float4*)(vp + j4 * 4);
                o[j4 * 4 + 0] += p * vv.x;
                o[j4 * 4 + 1] += p * vv.y;
                o[j4 * 4 + 2] += p * vv.z;
                o[j4 * 4 + 3] += p * vv.w;
            }
        }
    }

    const float inv_l = 1.f / l;
    const int q = q0 + r;
    const int b = bh >> 4;
    const int h = bh & 15;
    float* og = g_attn + ((size_t)(b * T_ + q)) * D_MODEL + h * DKH + cg * 16;
    #pragma unroll
    for (int j4 = 0; j4 < 4; j4++) {
        float4 ov;
        ov.x = o[j4 * 4 + 0] * inv_l;
        ov.y = o[j4 * 4 + 1] * inv_l;
        ov.z = o[j4 * 4 + 2] * inv_l;
        ov.w = o[j4 * 4 + 3] * inv_l;
        *(float4*)(og + j4 * 4) = ov;
    }
}

// ---------------------------------------------------------------------------
extern "C" void kernel_launch(void* const* d_in, const int* in_sizes, int n_in,
                              void* d_out, int out_size)
{
    const float* x     = (const float*)d_in[0];   // (4,2048,1024)
    const float* w_qkv = (const float*)d_in[1];   // (1024,3072)
    const float* w_out = (const float*)d_in[2];   // (1024,1024)
    float* out = (float*)d_out;                   // (4,2048,1024)

    // 1) QKV projection (HMMA, in-kernel bf16 split), scatter into q/k/v
    gemm_mma<0><<<dim3(N_QKV / 128, M_TOT / 128), 256>>>(
        x, w_qkv, nullptr, N_QKV);

    // 2) causal flash attention -> g_attn (B,T,D)
    attn_kernel<<<dim3(T_ / 64, B_ * N_HEADS), 256>>>();

    // 3) output projection (HMMA, in-kernel bf16 split) -> d_out
    gemm_mma<1><<<dim3(D_MODEL / 128, M_TOT / 128), 256>>>(
        nullptr, w_out, out, D_MODEL);
}

// round 8
// speedup vs baseline: 1.1942x; 1.1849x over previous
#include <cuda_runtime.h>
#include <cuda_bf16.h>
#include <cstdint>

#define D_MODEL 1024
#define N_HEADS 16
#define DKH     64
#define B_      4
#define T_      2048
#define M_TOT   (B_ * T_)        // 8192
#define N_QKV   (3 * D_MODEL)    // 3072
#define GK      1024

// ---------------- scratch (device globals; no allocation allowed) ----------
__device__ float g_q[(size_t)B_ * N_HEADS * T_ * DKH];
__device__ float g_k[(size_t)B_ * N_HEADS * T_ * DKH];
__device__ float g_v[(size_t)B_ * N_HEADS * T_ * DKH];
__device__ float g_attn[(size_t)M_TOT * D_MODEL];

// ============================ helpers ======================================
#define MMA_BF16(D, A, b0, b1) \
    asm volatile("mma.sync.aligned.m16n8k16.row.col.f32.bf16.bf16.f32 " \
        "{%0,%1,%2,%3}, {%4,%5,%6,%7}, {%8,%9}, {%0,%1,%2,%3};" \
        : "+f"((D)[0]), "+f"((D)[1]), "+f"((D)[2]), "+f"((D)[3]) \
        : "r"((A)[0]), "r"((A)[1]), "r"((A)[2]), "r"((A)[3]), "r"(b0), "r"(b1))

__device__ __forceinline__ void bf16_split(float x, unsigned short& h, unsigned short& l)
{
    __nv_bfloat16 hb = __float2bfloat16(x);
    h = __bfloat16_as_ushort(hb);
    l = __bfloat16_as_ushort(__float2bfloat16(x - __bfloat162float(hb)));
}

// ===================== double-buffered bf16 HMMA GEMM ======================
// C[M,N] = A[M,K](fp32) @ B[K,N](fp32), in-register 2-term bf16 split:
//   C = AhBh + AhBl + AlBh   (fp32 accumulate)
// CTA 128x128, 8 warps (2x4), warp tile 64x32, BK=16, 2-stage pipeline.
// Smem stride 18 bf16 (9 words, odd) -> conflict-free B-transpose STS.
#define BKS  16
#define NST  (GK / BKS)   // 64
#define AST  18

template<int MODE>
__global__ __launch_bounds__(256)
void gemm_mma(const float* __restrict__ Ap, const float* __restrict__ Bp,
              float* __restrict__ Cp, int N)
{
    __shared__ __nv_bfloat16 sA[2][2][128][AST];   // [buf][hi/lo][m][k]  9 KB each
    __shared__ __nv_bfloat16 sB[2][2][128][AST];   // [buf][hi/lo][n][k]

    const int tid  = threadIdx.x;
    const int wid  = tid >> 5;
    const int lane = tid & 31;
    const int wm   = wid & 1;
    const int wn   = wid >> 1;
    const int gid  = lane >> 2;
    const int tig  = lane & 3;
    const int row0 = blockIdx.y * 128;
    const int col0 = blockIdx.x * 128;

    const float* A = (MODE == 1) ? g_attn : Ap;

    float d[4][4][4];
    #pragma unroll
    for (int i = 0; i < 4; i++)
        #pragma unroll
        for (int j = 0; j < 4; j++)
            #pragma unroll
            for (int e = 0; e < 4; e++) d[i][j][e] = 0.f;

    // A: 128 rows x 16 cols = 512 float4; thread does rows ar0, ar0+64.
    const int ar0 = tid >> 2, ac0 = (tid & 3) * 4;
    // B: 16 k-rows x 128 n; warp w does k = w, w+8; lane does n = lane+32c.
    float4 va[2];
    float  vb[2][4];

    // ---- prologue: load + store stage 0 ----
    #pragma unroll
    for (int i = 0; i < 2; i++)
        va[i] = *(const float4*)(A + (size_t)(row0 + ar0 + i * 64) * GK + ac0);
    #pragma unroll
    for (int jj = 0; jj < 2; jj++)
        #pragma unroll
        for (int c = 0; c < 4; c++)
            vb[jj][c] = Bp[(size_t)(wid + 8 * jj) * N + col0 + lane + 32 * c];

    #pragma unroll
    for (int i = 0; i < 2; i++) {
        const int ra = ar0 + i * 64;
        const float xs[4] = {va[i].x, va[i].y, va[i].z, va[i].w};
        #pragma unroll
        for (int j = 0; j < 2; j++) {     // two 32-bit stores (4B aligned)
            unsigned short h0, l0, h1, l1;
            bf16_split(xs[2 * j + 0], h0, l0);
            bf16_split(xs[2 * j + 1], h1, l1);
            *(uint32_t*)&sA[0][0][ra][ac0 + 2 * j] = (uint32_t)h0 | ((uint32_t)h1 << 16);
            *(uint32_t*)&sA[0][1][ra][ac0 + 2 * j] = (uint32_t)l0 | ((uint32_t)l1 << 16);
        }
    }
    #pragma unroll
    for (int jj = 0; jj < 2; jj++)
        #pragma unroll
        for (int c = 0; c < 4; c++) {
            unsigned short hh, ll;
            bf16_split(vb[jj][c], hh, ll);
            sB[0][0][lane + 32 * c][wid + 8 * jj] = __ushort_as_bfloat16(hh);
            sB[0][1][lane + 32 * c][wid + 8 * jj] = __ushort_as_bfloat16(ll);
        }
    __syncthreads();

    const int kb = tig * 2;
    for (int kt = 0; kt < NST; kt++) {
        const int buf = kt & 1;
        // ---- prefetch stage kt+1 (LDG in flight during compute) ----
        if (kt + 1 < NST) {
            const int k0 = (kt + 1) * BKS;
            #pragma unroll
            for (int i = 0; i < 2; i++)
                va[i] = *(const float4*)(A + (size_t)(row0 + ar0 + i * 64) * GK + k0 + ac0);
            #pragma unroll
            for (int jj = 0; jj < 2; jj++)
                #pragma unroll
                for (int c = 0; c < 4; c++)
                    vb[jj][c] = Bp[(size_t)(k0 + wid + 8 * jj) * N + col0 + lane + 32 * c];
        }

        // ---- compute stage kt (K=16: one MMA k-step) ----
        uint32_t Ah[4][4], Al[4][4];
        #pragma unroll
        for (int mi = 0; mi < 4; mi++) {
            const int r0 = wm * 64 + mi * 16 + gid;
            Ah[mi][0] = *(const uint32_t*)&sA[buf][0][r0][kb];
            Ah[mi][1] = *(const uint32_t*)&sA[buf][0][r0 + 8][kb];
            Ah[mi][2] = *(const uint32_t*)&sA[buf][0][r0][kb + 8];
            Ah[mi][3] = *(const uint32_t*)&sA[buf][0][r0 + 8][kb + 8];
            Al[mi][0] = *(const uint32_t*)&sA[buf][1][r0][kb];
            Al[mi][1] = *(const uint32_t*)&sA[buf][1][r0 + 8][kb];
            Al[mi][2] = *(const uint32_t*)&sA[buf][1][r0][kb + 8];
            Al[mi][3] = *(const uint32_t*)&sA[buf][1][r0 + 8][kb + 8];
        }
        uint32_t Bh[4][2], Bl[4][2];
        #pragma unroll
        for (int ng = 0; ng < 4; ng++) {
            const int nr = wn * 32 + ng * 8 + gid;
            Bh[ng][0] = *(const uint32_t*)&sB[buf][0][nr][kb];
            Bh[ng][1] = *(const uint32_t*)&sB[buf][0][nr][kb + 8];
            Bl[ng][0] = *(const uint32_t*)&sB[buf][1][nr][kb];
            Bl[ng][1] = *(const uint32_t*)&sB[buf][1][nr][kb + 8];
        }
        #pragma unroll
        for (int mi = 0; mi < 4; mi++)
            #pragma unroll
            for (int ng = 0; ng < 4; ng++) {
                MMA_BF16(d[mi][ng], Ah[mi], Bh[ng][0], Bh[ng][1]);
                MMA_BF16(d[mi][ng], Ah[mi], Bl[ng][0], Bl[ng][1]);
                MMA_BF16(d[mi][ng], Al[mi], Bh[ng][0], Bh[ng][1]);
            }

        // ---- store stage kt+1 into the other buffer ----
        if (kt + 1 < NST) {
            const int nb = buf ^ 1;
            #pragma unroll
            for (int i = 0; i < 2; i++) {
                const int ra = ar0 + i * 64;
                const float xs[4] = {va[i].x, va[i].y, va[i].z, va[i].w};
                #pragma unroll
                for (int j = 0; j < 2; j++) {
                    unsigned short h0, l0, h1, l1;
                    bf16_split(xs[2 * j + 0], h0, l0);
                    bf16_split(xs[2 * j + 1], h1, l1);
                    *(uint32_t*)&sA[nb][0][ra][ac0 + 2 * j] = (uint32_t)h0 | ((uint32_t)h1 << 16);
                    *(uint32_t*)&sA[nb][1][ra][ac0 + 2 * j] = (uint32_t)l0 | ((uint32_t)l1 << 16);
                }
            }
            #pragma unroll
            for (int jj = 0; jj < 2; jj++)
                #pragma unroll
                for (int c = 0; c < 4; c++) {
                    unsigned short hh, ll;
                    bf16_split(vb[jj][c], hh, ll);
                    sB[nb][0][lane + 32 * c][wid + 8 * jj] = __ushort_as_bfloat16(hh);
                    sB[nb][1][lane + 32 * c][wid + 8 * jj] = __ushort_as_bfloat16(ll);
                }
        }
        __syncthreads();
    }

    // ---------------- epilogue (R6-proven mapping) ----------------
    #pragma unroll
    for (int mi = 0; mi < 4; mi++)
        #pragma unroll
        for (int ng = 0; ng < 4; ng++) {
            const int n = col0 + wn * 32 + ng * 8 + tig * 2;
            #pragma unroll
            for (int h = 0; h < 2; h++) {
                const int m = row0 + wm * 64 + mi * 16 + gid + h * 8;
                float2 v;
                v.x = d[mi][ng][h * 2 + 0];
                v.y = d[mi][ng][h * 2 + 1];
                if (MODE == 0) {
                    int b = m >> 11, t = m & (T_ - 1);
                    int sidx = n >> 10;
                    int dmi  = n & (D_MODEL - 1);
                    int hh = dmi >> 6, dk = dmi & (DKH - 1);
                    float* base = (sidx == 0) ? g_q : (sidx == 1) ? g_k : g_v;
                    *(float2*)(base + (((size_t)((b << 4) + hh)) * T_ + t) * DKH + dk) = v;
                } else {
                    *(float2*)(Cp + (size_t)m * N + n) = v;
                }
            }
        }
}

// ---------------------------------------------------------------------------
// Causal flash attention, fp32 (R1-proven, unchanged). BM=BN=64, d_k=64.
// ---------------------------------------------------------------------------
#define SM_STRIDE 68

__global__ __launch_bounds__(256)
void attn_kernel()
{
    const int bh  = blockIdx.y;
    const int q0  = blockIdx.x * 64;
    const int tid = threadIdx.x;
    const int r   = tid >> 2;
    const int cg  = tid & 3;

    __shared__ float Qs[64 * SM_STRIDE];
    __shared__ float Kt[64 * SM_STRIDE];
    __shared__ float Vs[64 * SM_STRIDE];
    __shared__ float Ps[64 * SM_STRIDE];

    const float* Qg = g_q + ((size_t)bh * T_ + q0) * DKH;
    const float* Kg = g_k + (size_t)bh * T_ * DKH;
    const float* Vg = g_v + (size_t)bh * T_ * DKH;

    const float SCALE = 0.125f;
    const float LOG2E = 1.4426950408889634f;

    #pragma unroll
    for (int i = 0; i < 4; i++) {
        int f = tid + i * 256;
        int c = f >> 4;
        int d = (f & 15) * 4;
        float4 q4 = *(const float4*)(Qg + (size_t)c * DKH + d);
        Qs[c * SM_STRIDE + d + 0] = q4.x * SCALE;
        Qs[c * SM_STRIDE + d + 1] = q4.y * SCALE;
        Qs[c * SM_STRIDE + d + 2] = q4.z * SCALE;
        Qs[c * SM_STRIDE + d + 3] = q4.w * SCALE;
    }

    float o[16];
    #pragma unroll
    for (int j = 0; j < 16; j++) o[j] = 0.f;
    float m = -1e30f, l = 0.f;

    const int ntiles = (q0 >> 6) + 1;

    for (int kt_i = 0; kt_i < ntiles; ++kt_i) {
        const int k0 = kt_i * 64;
        __syncthreads();

        #pragma unroll
        for (int i = 0; i < 4; i++) {
            int f = tid + i * 256;
            int c = f >> 4;
            int d = (f & 15) * 4;
            float4 k4 = *(const float4*)(Kg + (size_t)(k0 + c) * DKH + d);
            Kt[(d + 0) * SM_STRIDE + c] = k4.x;
            Kt[(d + 1) * SM_STRIDE + c] = k4.y;
            Kt[(d + 2) * SM_STRIDE + c] = k4.z;
            Kt[(d + 3) * SM_STRIDE + c] = k4.w;
            float4 v4 = *(const float4*)(Vg + (size_t)(k0 + c) * DKH + d);
            *(float4*)(&Vs[c * SM_STRIDE + d]) = v4;
        }
        __syncthreads();

        float s[16];
        #pragma unroll
        for (int j = 0; j < 16; j++) s[j] = 0.f;
        #pragma unroll 8
        for (int k = 0; k < 64; k++) {
            float qv = Qs[r * SM_STRIDE + k];
            const float* kp = &Kt[k * SM_STRIDE + cg * 16];
            #pragma unroll
            for (int j4 = 0; j4 < 4; j4++) {
                float4 kv = *(const float4*)(kp + j4 * 4);
                s[j4 * 4 + 0] += qv * kv.x;
                s[j4 * 4 + 1] += qv * kv.y;
                s[j4 * 4 + 2] += qv * kv.z;
                s[j4 * 4 + 3] += qv * kv.w;
            }
        }

        if (k0 == q0) {
            #pragma unroll
            for (int j = 0; j < 16; j++)
                if (cg * 16 + j > r) s[j] = -1e30f;
        }

        float mt = s[0];
        #pragma unroll
        for (int j = 1; j < 16; j++) mt = fmaxf(mt, s[j]);
        mt = fmaxf(mt, __shfl_xor_sync(0xffffffff, mt, 1));
        mt = fmaxf(mt, __shfl_xor_sync(0xffffffff, mt, 2));
        float mn    = fmaxf(m, mt);
        float alpha = exp2f((m - mn) * LOG2E);
        float rs = 0.f;
        #pragma unroll
        for (int j = 0; j < 16; j++) {
            float p = exp2f((s[j] - mn) * LOG2E);
            s[j] = p;
            rs  += p;
        }
        rs += __shfl_xor_sync(0xffffffff, rs, 1);
        rs += __shfl_xor_sync(0xffffffff, rs, 2);
        l = l * alpha + rs;
        m = mn;
        #pragma unroll
        for (int j = 0; j < 16; j++) o[j] *= alpha;

        #pragma unroll
        for (int j = 0; j < 16; j++)
            Ps[r * SM_STRIDE + cg * 16 + j] = s[j];
        __syncwarp();

        #pragma unroll 4
        for (int c = 0; c < 64; c++) {
            float p = Ps[r * SM_STRIDE + c];
            const float* vp = &Vs[c * SM_STRIDE + cg * 16];
            #pragma unroll
            for (int j4 = 0; j4 < 4; j4++) {
                float4 vv = *(const float4*)(vp + j4 * 4);
                o[j4 * 4 + 0] += p * vv.x;
                o[j4 * 4 + 1] += p * vv.y;
                o[j4 * 4 + 2] += p * vv.z;
                o[j4 * 4 + 3] += p * vv.w;
            }
        }
    }

    const float inv_l = 1.f / l;
    const int q = q0 + r;
    const int b = bh >> 4;
    const int h = bh & 15;
    float* og = g_attn + ((size_t)(b * T_ + q)) * D_MODEL + h * DKH + cg * 16;
    #pragma unroll
    for (int j4 = 0; j4 < 4; j4++) {
        float4 ov;
        ov.x = o[j4 * 4 + 0] * inv_l;
        ov.y = o[j4 * 4 + 1] * inv_l;
        ov.z = o[j4 * 4 + 2] * inv_l;
        ov.w = o[j4 * 4 + 3] * inv_l;
        *(float4*)(og + j4 * 4) = ov;
    }
}

// ---------------------------------------------------------------------------
extern "C" void kernel_launch(void* const* d_in, const int* in_sizes, int n_in,
                              void* d_out, int out_size)
{
    const float* x     = (const float*)d_in[0];
    const float* w_qkv = (const float*)d_in[1];
    const float* w_out = (const float*)d_in[2];
    float* out = (float*)d_out;

    gemm_mma<0><<<dim3(N_QKV / 128, M_TOT / 128), 256>>>(x, w_qkv, nullptr, N_QKV);
    attn_kernel<<<dim3(T_ / 64, B_ * N_HEADS), 256>>>();
    gemm_mma<1><<<dim3(D_MODEL / 128, M_TOT / 128), 256>>>(nullptr, w_out, out, D_MODEL);
}

// round 9
// speedup vs baseline: 4.7368x; 3.9666x over previous
#include <cuda_runtime.h>
#include <cuda_bf16.h>
#include <cstdint>

#define D_MODEL 1024
#define N_HEADS 16
#define DKH     64
#define B_      4
#define T_      2048
#define M_TOT   (B_ * T_)        // 8192
#define N_QKV   (3 * D_MODEL)    // 3072
#define GK      1024

// ---------------- scratch (device globals; no allocation allowed) ----------
__device__ float g_q[(size_t)B_ * N_HEADS * T_ * DKH];
__device__ float g_k[(size_t)B_ * N_HEADS * T_ * DKH];
__device__ float g_v[(size_t)B_ * N_HEADS * T_ * DKH];
__device__ float g_attn[(size_t)M_TOT * D_MODEL];

// ============================ helpers ======================================
#define MMA_BF16(D, A, b0, b1) \
    asm volatile("mma.sync.aligned.m16n8k16.row.col.f32.bf16.bf16.f32 " \
        "{%0,%1,%2,%3}, {%4,%5,%6,%7}, {%8,%9}, {%0,%1,%2,%3};" \
        : "+f"((D)[0]), "+f"((D)[1]), "+f"((D)[2]), "+f"((D)[3]) \
        : "r"((A)[0]), "r"((A)[1]), "r"((A)[2]), "r"((A)[3]), "r"(b0), "r"(b1))

__device__ __forceinline__ void bf16_split(float x, unsigned short& h, unsigned short& l)
{
    __nv_bfloat16 hb = __float2bfloat16(x);
    h = __bfloat16_as_ushort(hb);
    l = __bfloat16_as_ushort(__float2bfloat16(x - __bfloat162float(hb)));
}
// pack (a at k, b at k+1) into hi/lo bf16x2 regs (low half = a)
__device__ __forceinline__ void split2(float a, float b, uint32_t& hi, uint32_t& lo)
{
    unsigned short ha, la, hb, lb;
    bf16_split(a, ha, la);
    bf16_split(b, hb, lb);
    hi = (uint32_t)ha | ((uint32_t)hb << 16);
    lo = (uint32_t)la | ((uint32_t)lb << 16);
}

// ===================== double-buffered bf16 HMMA GEMM (R8, proven) =========
#define BKS  16
#define NST  (GK / BKS)
#define AST  18

template<int MODE>
__global__ __launch_bounds__(256)
void gemm_mma(const float* __restrict__ Ap, const float* __restrict__ Bp,
              float* __restrict__ Cp, int N)
{
    __shared__ __nv_bfloat16 sA[2][2][128][AST];
    __shared__ __nv_bfloat16 sB[2][2][128][AST];

    const int tid  = threadIdx.x;
    const int wid  = tid >> 5;
    const int lane = tid & 31;
    const int wm   = wid & 1;
    const int wn   = wid >> 1;
    const int gid  = lane >> 2;
    const int tig  = lane & 3;
    const int row0 = blockIdx.y * 128;
    const int col0 = blockIdx.x * 128;

    const float* A = (MODE == 1) ? g_attn : Ap;

    float d[4][4][4];
    #pragma unroll
    for (int i = 0; i < 4; i++)
        #pragma unroll
        for (int j = 0; j < 4; j++)
            #pragma unroll
            for (int e = 0; e < 4; e++) d[i][j][e] = 0.f;

    const int ar0 = tid >> 2, ac0 = (tid & 3) * 4;
    float4 va[2];
    float  vb[2][4];

    #pragma unroll
    for (int i = 0; i < 2; i++)
        va[i] = *(const float4*)(A + (size_t)(row0 + ar0 + i * 64) * GK + ac0);
    #pragma unroll
    for (int jj = 0; jj < 2; jj++)
        #pragma unroll
        for (int c = 0; c < 4; c++)
            vb[jj][c] = Bp[(size_t)(wid + 8 * jj) * N + col0 + lane + 32 * c];

    #pragma unroll
    for (int i = 0; i < 2; i++) {
        const int ra = ar0 + i * 64;
        const float xs[4] = {va[i].x, va[i].y, va[i].z, va[i].w};
        #pragma unroll
        for (int j = 0; j < 2; j++) {
            unsigned short h0, l0, h1, l1;
            bf16_split(xs[2 * j + 0], h0, l0);
            bf16_split(xs[2 * j + 1], h1, l1);
            *(uint32_t*)&sA[0][0][ra][ac0 + 2 * j] = (uint32_t)h0 | ((uint32_t)h1 << 16);
            *(uint32_t*)&sA[0][1][ra][ac0 + 2 * j] = (uint32_t)l0 | ((uint32_t)l1 << 16);
        }
    }
    #pragma unroll
    for (int jj = 0; jj < 2; jj++)
        #pragma unroll
        for (int c = 0; c < 4; c++) {
            unsigned short hh, ll;
            bf16_split(vb[jj][c], hh, ll);
            sB[0][0][lane + 32 * c][wid + 8 * jj] = __ushort_as_bfloat16(hh);
            sB[0][1][lane + 32 * c][wid + 8 * jj] = __ushort_as_bfloat16(ll);
        }
    __syncthreads();

    const int kb = tig * 2;
    for (int kt = 0; kt < NST; kt++) {
        const int buf = kt & 1;
        if (kt + 1 < NST) {
            const int k0 = (kt + 1) * BKS;
            #pragma unroll
            for (int i = 0; i < 2; i++)
                va[i] = *(const float4*)(A + (size_t)(row0 + ar0 + i * 64) * GK + k0 + ac0);
            #pragma unroll
            for (int jj = 0; jj < 2; jj++)
                #pragma unroll
                for (int c = 0; c < 4; c++)
                    vb[jj][c] = Bp[(size_t)(k0 + wid + 8 * jj) * N + col0 + lane + 32 * c];
        }

        uint32_t Ah[4][4], Al[4][4];
        #pragma unroll
        for (int mi = 0; mi < 4; mi++) {
            const int r0 = wm * 64 + mi * 16 + gid;
            Ah[mi][0] = *(const uint32_t*)&sA[buf][0][r0][kb];
            Ah[mi][1] = *(const uint32_t*)&sA[buf][0][r0 + 8][kb];
            Ah[mi][2] = *(const uint32_t*)&sA[buf][0][r0][kb + 8];
            Ah[mi][3] = *(const uint32_t*)&sA[buf][0][r0 + 8][kb + 8];
            Al[mi][0] = *(const uint32_t*)&sA[buf][1][r0][kb];
            Al[mi][1] = *(const uint32_t*)&sA[buf][1][r0 + 8][kb];
            Al[mi][2] = *(const uint32_t*)&sA[buf][1][r0][kb + 8];
            Al[mi][3] = *(const uint32_t*)&sA[buf][1][r0 + 8][kb + 8];
        }
        uint32_t Bh[4][2], Bl[4][2];
        #pragma unroll
        for (int ng = 0; ng < 4; ng++) {
            const int nr = wn * 32 + ng * 8 + gid;
            Bh[ng][0] = *(const uint32_t*)&sB[buf][0][nr][kb];
            Bh[ng][1] = *(const uint32_t*)&sB[buf][0][nr][kb + 8];
            Bl[ng][0] = *(const uint32_t*)&sB[buf][1][nr][kb];
            Bl[ng][1] = *(const uint32_t*)&sB[buf][1][nr][kb + 8];
        }
        #pragma unroll
        for (int mi = 0; mi < 4; mi++)
            #pragma unroll
            for (int ng = 0; ng < 4; ng++) {
                MMA_BF16(d[mi][ng], Ah[mi], Bh[ng][0], Bh[ng][1]);
                MMA_BF16(d[mi][ng], Ah[mi], Bl[ng][0], Bl[ng][1]);
                MMA_BF16(d[mi][ng], Al[mi], Bh[ng][0], Bh[ng][1]);
            }

        if (kt + 1 < NST) {
            const int nb = buf ^ 1;
            #pragma unroll
            for (int i = 0; i < 2; i++) {
                const int ra = ar0 + i * 64;
                const float xs[4] = {va[i].x, va[i].y, va[i].z, va[i].w};
                #pragma unroll
                for (int j = 0; j < 2; j++) {
                    unsigned short h0, l0, h1, l1;
                    bf16_split(xs[2 * j + 0], h0, l0);
                    bf16_split(xs[2 * j + 1], h1, l1);
                    *(uint32_t*)&sA[nb][0][ra][ac0 + 2 * j] = (uint32_t)h0 | ((uint32_t)h1 << 16);
                    *(uint32_t*)&sA[nb][1][ra][ac0 + 2 * j] = (uint32_t)l0 | ((uint32_t)l1 << 16);
                }
            }
            #pragma unroll
            for (int jj = 0; jj < 2; jj++)
                #pragma unroll
                for (int c = 0; c < 4; c++) {
                    unsigned short hh, ll;
                    bf16_split(vb[jj][c], hh, ll);
                    sB[nb][0][lane + 32 * c][wid + 8 * jj] = __ushort_as_bfloat16(hh);
                    sB[nb][1][lane + 32 * c][wid + 8 * jj] = __ushort_as_bfloat16(ll);
                }
        }
        __syncthreads();
    }

    #pragma unroll
    for (int mi = 0; mi < 4; mi++)
        #pragma unroll
        for (int ng = 0; ng < 4; ng++) {
            const int n = col0 + wn * 32 + ng * 8 + tig * 2;
            #pragma unroll
            for (int h = 0; h < 2; h++) {
                const int m = row0 + wm * 64 + mi * 16 + gid + h * 8;
                float2 v;
                v.x = d[mi][ng][h * 2 + 0];
                v.y = d[mi][ng][h * 2 + 1];
                if (MODE == 0) {
                    int b = m >> 11, t = m & (T_ - 1);
                    int sidx = n >> 10;
                    int dmi  = n & (D_MODEL - 1);
                    int hh = dmi >> 6, dk = dmi & (DKH - 1);
                    float* base = (sidx == 0) ? g_q : (sidx == 1) ? g_k : g_v;
                    *(float2*)(base + (((size_t)((b << 4) + hh)) * T_ + t) * DKH + dk) = v;
                } else {
                    *(float2*)(Cp + (size_t)m * N + n) = v;
                }
            }
        }
}

// ===================== bf16 HMMA causal flash attention ====================
// 128 q-rows/CTA, 8 warps x 16 rows. 64-key tiles. All matmuls hi/lo split.
// K smem [key][dk] (native B layout), V^T smem [dk][key].
// Stride 72 elems (36 words): frag LDS bank = 4*gid+tig+8*ks -> conflict-free.
#define VST 72

__global__ __launch_bounds__(256)
void attn_mma()
{
    __shared__ __align__(16) __nv_bfloat16 sKh[64][VST], sKl[64][VST];
    __shared__ __align__(16) __nv_bfloat16 sVh[64][VST], sVl[64][VST];

    const int bh  = blockIdx.y;
    const int q0  = blockIdx.x * 128;
    const int tid = threadIdx.x;
    const int wid = tid >> 5;
    const int lane = tid & 31;
    const int gid = lane >> 2;
    const int tig = lane & 3;

    const float* Qg = g_q + ((size_t)bh * T_ + q0) * DKH;
    const float* Kg = g_k + (size_t)bh * T_ * DKH;
    const float* Vg = g_v + (size_t)bh * T_ * DKH;
    const float LOG2E = 1.4426950408889634f;

    // ---- Q fragments (staged through sKh/sKl in two 64-row passes) ----
    uint32_t Qh[4][4], Ql[4][4];
    #pragma unroll
    for (int pass = 0; pass < 2; pass++) {
        #pragma unroll
        for (int i = 0; i < 4; i++) {
            int c = tid + i * 256;
            int r = c >> 4, dk0 = (c & 15) * 4;
            float4 q4 = *(const float4*)(Qg + (size_t)(pass * 64 + r) * DKH + dk0);
            const float xs[4] = {q4.x * 0.125f, q4.y * 0.125f, q4.z * 0.125f, q4.w * 0.125f};
            ushort4 h4, l4;
            bf16_split(xs[0], h4.x, l4.x); bf16_split(xs[1], h4.y, l4.y);
            bf16_split(xs[2], h4.z, l4.z); bf16_split(xs[3], h4.w, l4.w);
            *(ushort4*)&sKh[r][dk0] = h4;
            *(ushort4*)&sKl[r][dk0] = l4;
        }
        __syncthreads();
        if ((wid >> 2) == pass) {
            const int rb = (wid & 3) * 16 + gid;
            #pragma unroll
            for (int ks = 0; ks < 4; ks++) {
                const int kb = ks * 16 + tig * 2;
                Qh[ks][0] = *(const uint32_t*)&sKh[rb][kb];
                Qh[ks][1] = *(const uint32_t*)&sKh[rb + 8][kb];
                Qh[ks][2] = *(const uint32_t*)&sKh[rb][kb + 8];
                Qh[ks][3] = *(const uint32_t*)&sKh[rb + 8][kb + 8];
                Ql[ks][0] = *(const uint32_t*)&sKl[rb][kb];
                Ql[ks][1] = *(const uint32_t*)&sKl[rb + 8][kb];
                Ql[ks][2] = *(const uint32_t*)&sKl[rb][kb + 8];
                Ql[ks][3] = *(const uint32_t*)&sKl[rb + 8][kb + 8];
            }
        }
        __syncthreads();
    }

    float O[8][4];
    #pragma unroll
    for (int i = 0; i < 8; i++)
        #pragma unroll
        for (int e = 0; e < 4; e++) O[i][e] = 0.f;
    float mr[2] = {-1e30f, -1e30f}, lr[2] = {0.f, 0.f};

    const int qA = q0 + wid * 16 + gid;      // row of c0/c1 (c2/c3 = qA+8)
    const int ntiles = (q0 >> 6) + 2;

    for (int t = 0; t < ntiles; t++) {
        const int k0 = t * 64;
        // global loads first (in flight across the barrier)
        float4 kv[4], vv[4];
        #pragma unroll
        for (int i = 0; i < 4; i++) {
            int c = tid + i * 256;
            int r = c >> 4, dk0 = (c & 15) * 4;
            kv[i] = *(const float4*)(Kg + (size_t)(k0 + r) * DKH + dk0);
            vv[i] = *(const float4*)(Vg + (size_t)(k0 + r) * DKH + dk0);
        }
        __syncthreads();   // prev tile's compute done
        #pragma unroll
        for (int i = 0; i < 4; i++) {
            int c = tid + i * 256;
            int r = c >> 4, dk0 = (c & 15) * 4;
            ushort4 h4, l4;
            bf16_split(kv[i].x, h4.x, l4.x); bf16_split(kv[i].y, h4.y, l4.y);
            bf16_split(kv[i].z, h4.z, l4.z); bf16_split(kv[i].w, h4.w, l4.w);
            *(ushort4*)&sKh[r][dk0] = h4;
            *(ushort4*)&sKl[r][dk0] = l4;
            const float vs[4] = {vv[i].x, vv[i].y, vv[i].z, vv[i].w};
            #pragma unroll
            for (int j = 0; j < 4; j++) {
                unsigned short hh, ll;
                bf16_split(vs[j], hh, ll);
                sVh[dk0 + j][r] = __ushort_as_bfloat16(hh);   // V^T
                sVl[dk0 + j][r] = __ushort_as_bfloat16(ll);
            }
        }
        __syncthreads();

        if (k0 <= q0 + wid * 16 + 15) {   // warp has unmasked rows this tile
            // ---- S = (Q*scale) @ K^T ----
            float S[8][4];
            #pragma unroll
            for (int i = 0; i < 8; i++)
                #pragma unroll
                for (int e = 0; e < 4; e++) S[i][e] = 0.f;
            #pragma unroll
            for (int ks = 0; ks < 4; ks++) {
                const int kb = ks * 16 + tig * 2;
                #pragma unroll
                for (int ng = 0; ng < 8; ng++) {
                    const int nr = ng * 8 + gid;
                    uint32_t bh0 = *(const uint32_t*)&sKh[nr][kb];
                    uint32_t bh1 = *(const uint32_t*)&sKh[nr][kb + 8];
                    uint32_t bl0 = *(const uint32_t*)&sKl[nr][kb];
                    uint32_t bl1 = *(const uint32_t*)&sKl[nr][kb + 8];
                    MMA_BF16(S[ng], Qh[ks], bh0, bh1);
                    MMA_BF16(S[ng], Qh[ks], bl0, bl1);
                    MMA_BF16(S[ng], Ql[ks], bh0, bh1);
                }
            }
            // ---- causal mask (only near-diagonal tiles) ----
            if (k0 + 63 > q0 + wid * 16) {
                #pragma unroll
                for (int ng = 0; ng < 8; ng++)
                    #pragma unroll
                    for (int e = 0; e < 4; e++) {
                        const int key = k0 + ng * 8 + tig * 2 + (e & 1);
                        const int q   = qA + (e >> 1) * 8;
                        if (key > q) S[ng][e] = -1e30f;
                    }
            }
            // ---- online softmax (two rows per thread) ----
            #pragma unroll
            for (int h = 0; h < 2; h++) {
                float mt = -1e30f;
                #pragma unroll
                for (int ng = 0; ng < 8; ng++)
                    mt = fmaxf(mt, fmaxf(S[ng][2 * h], S[ng][2 * h + 1]));
                mt = fmaxf(mt, __shfl_xor_sync(0xffffffff, mt, 1));
                mt = fmaxf(mt, __shfl_xor_sync(0xffffffff, mt, 2));
                const float mn = fmaxf(mr[h], mt);
                const float alpha = exp2f((mr[h] - mn) * LOG2E);
                float rs = 0.f;
                #pragma unroll
                for (int ng = 0; ng < 8; ng++) {
                    float p0 = exp2f((S[ng][2 * h] - mn) * LOG2E);
                    float p1 = exp2f((S[ng][2 * h + 1] - mn) * LOG2E);
                    S[ng][2 * h] = p0;
                    S[ng][2 * h + 1] = p1;
                    rs += p0 + p1;
                }
                rs += __shfl_xor_sync(0xffffffff, rs, 1);
                rs += __shfl_xor_sync(0xffffffff, rs, 2);
                lr[h] = lr[h] * alpha + rs;
                mr[h] = mn;
                #pragma unroll
                for (int ng = 0; ng < 8; ng++) {
                    O[ng][2 * h] *= alpha;
                    O[ng][2 * h + 1] *= alpha;
                }
            }
            // ---- O += P @ V  (P a-frags built in registers from S c-frags) ----
            #pragma unroll
            for (int ks = 0; ks < 4; ks++) {
                uint32_t Ph[4], Pl[4];
                split2(S[2 * ks][0],     S[2 * ks][1],     Ph[0], Pl[0]);
                split2(S[2 * ks][2],     S[2 * ks][3],     Ph[1], Pl[1]);
                split2(S[2 * ks + 1][0], S[2 * ks + 1][1], Ph[2], Pl[2]);
                split2(S[2 * ks + 1][2], S[2 * ks + 1][3], Ph[3], Pl[3]);
                const int kb = ks * 16 + tig * 2;
                #pragma unroll
                for (int ng = 0; ng < 8; ng++) {
                    const int nr = ng * 8 + gid;   // dk row of V^T
                    uint32_t vh0 = *(const uint32_t*)&sVh[nr][kb];
                    uint32_t vh1 = *(const uint32_t*)&sVh[nr][kb + 8];
                    uint32_t vl0 = *(const uint32_t*)&sVl[nr][kb];
                    uint32_t vl1 = *(const uint32_t*)&sVl[nr][kb + 8];
                    MMA_BF16(O[ng], Ph, vh0, vh1);
                    MMA_BF16(O[ng], Ph, vl0, vl1);
                    MMA_BF16(O[ng], Pl, vh0, vh1);
                }
            }
        }
    }

    // ---- epilogue: normalize + write (B,T,D) with head interleave ----
    const int b = bh >> 4, h = bh & 15;
    #pragma unroll
    for (int hh = 0; hh < 2; hh++) {
        const float inv = 1.f / lr[hh];
        const int q = qA + hh * 8;
        float* og = g_attn + ((size_t)(b * T_ + q)) * D_MODEL + h * DKH;
        #pragma unroll
        for (int ng = 0; ng < 8; ng++) {
            float2 v;
            v.x = O[ng][2 * hh] * inv;
            v.y = O[ng][2 * hh + 1] * inv;
            *(float2*)(og + ng * 8 + tig * 2) = v;
        }
    }
}

// ---------------------------------------------------------------------------
extern "C" void kernel_launch(void* const* d_in, const int* in_sizes, int n_in,
                              void* d_out, int out_size)
{
    const float* x     = (const float*)d_in[0];
    const float* w_qkv = (const float*)d_in[1];
    const float* w_out = (const float*)d_in[2];
    float* out = (float*)d_out;

    gemm_mma<0><<<dim3(N_QKV / 128, M_TOT / 128), 256>>>(x, w_qkv, nullptr, N_QKV);
    attn_mma<<<dim3(T_ / 128, B_ * N_HEADS), 256>>>();
    gemm_mma<1><<<dim3(D_MODEL / 128, M_TOT / 128), 256>>>(nullptr, w_out, out, D_MODEL);
}

// round 10
// speedup vs baseline: 5.2040x; 1.0986x over previous
#include <cuda_runtime.h>
#include <cuda_bf16.h>
#include <cstdint>

#define D_MODEL 1024
#define N_HEADS 16
#define DKH     64
#define B_      4
#define T_      2048
#define M_TOT   (B_ * T_)        // 8192
#define N_QKV   (3 * D_MODEL)    // 3072
#define GK      1024

// ---------------- scratch (device globals; no allocation allowed) ----------
// Q/K: bf16 hi/lo, [bh][t][dk] (Q pre-scaled by 0.125). V: [bh][dk][t].
__device__ __nv_bfloat16 g_qh[(size_t)64 * T_ * DKH];
__device__ __nv_bfloat16 g_ql[(size_t)64 * T_ * DKH];
__device__ __nv_bfloat16 g_kh[(size_t)64 * T_ * DKH];
__device__ __nv_bfloat16 g_kl[(size_t)64 * T_ * DKH];
__device__ __nv_bfloat16 g_vh[(size_t)64 * DKH * T_];
__device__ __nv_bfloat16 g_vl[(size_t)64 * DKH * T_];
__device__ float g_attn[(size_t)M_TOT * D_MODEL];

// ============================ helpers ======================================
#define MMA_BF16(D, A, b0, b1) \
    asm volatile("mma.sync.aligned.m16n8k16.row.col.f32.bf16.bf16.f32 " \
        "{%0,%1,%2,%3}, {%4,%5,%6,%7}, {%8,%9}, {%0,%1,%2,%3};" \
        : "+f"((D)[0]), "+f"((D)[1]), "+f"((D)[2]), "+f"((D)[3]) \
        : "r"((A)[0]), "r"((A)[1]), "r"((A)[2]), "r"((A)[3]), "r"(b0), "r"(b1))

__device__ __forceinline__ void bf16_split(float x, unsigned short& h, unsigned short& l)
{
    __nv_bfloat16 hb = __float2bfloat16(x);
    h = __bfloat16_as_ushort(hb);
    l = __bfloat16_as_ushort(__float2bfloat16(x - __bfloat162float(hb)));
}
// pack (a at k, b at k+1) into hi/lo bf16x2 regs (low half = a)
__device__ __forceinline__ void split2(float a, float b, uint32_t& hi, uint32_t& lo)
{
    unsigned short ha, la, hb, lb;
    bf16_split(a, ha, la);
    bf16_split(b, hb, lb);
    hi = (uint32_t)ha | ((uint32_t)hb << 16);
    lo = (uint32_t)la | ((uint32_t)lb << 16);
}

// ===================== double-buffered bf16 HMMA GEMM (R8, proven) =========
#define BKS  16
#define NST  (GK / BKS)
#define AST  18

template<int MODE>
__global__ __launch_bounds__(256)
void gemm_mma(const float* __restrict__ Ap, const float* __restrict__ Bp,
              float* __restrict__ Cp, int N)
{
    __shared__ __nv_bfloat16 sA[2][2][128][AST];
    __shared__ __nv_bfloat16 sB[2][2][128][AST];

    const int tid  = threadIdx.x;
    const int wid  = tid >> 5;
    const int lane = tid & 31;
    const int wm   = wid & 1;
    const int wn   = wid >> 1;
    const int gid  = lane >> 2;
    const int tig  = lane & 3;
    const int row0 = blockIdx.y * 128;
    const int col0 = blockIdx.x * 128;

    const float* A = (MODE == 1) ? g_attn : Ap;

    float d[4][4][4];
    #pragma unroll
    for (int i = 0; i < 4; i++)
        #pragma unroll
        for (int j = 0; j < 4; j++)
            #pragma unroll
            for (int e = 0; e < 4; e++) d[i][j][e] = 0.f;

    const int ar0 = tid >> 2, ac0 = (tid & 3) * 4;
    float4 va[2];
    float  vb[2][4];

    #pragma unroll
    for (int i = 0; i < 2; i++)
        va[i] = *(const float4*)(A + (size_t)(row0 + ar0 + i * 64) * GK + ac0);
    #pragma unroll
    for (int jj = 0; jj < 2; jj++)
        #pragma unroll
        for (int c = 0; c < 4; c++)
            vb[jj][c] = Bp[(size_t)(wid + 8 * jj) * N + col0 + lane + 32 * c];

    #pragma unroll
    for (int i = 0; i < 2; i++) {
        const int ra = ar0 + i * 64;
        const float xs[4] = {va[i].x, va[i].y, va[i].z, va[i].w};
        #pragma unroll
        for (int j = 0; j < 2; j++) {
            uint32_t hi, lo;
            split2(xs[2 * j + 0], xs[2 * j + 1], hi, lo);
            *(uint32_t*)&sA[0][0][ra][ac0 + 2 * j] = hi;
            *(uint32_t*)&sA[0][1][ra][ac0 + 2 * j] = lo;
        }
    }
    #pragma unroll
    for (int jj = 0; jj < 2; jj++)
        #pragma unroll
        for (int c = 0; c < 4; c++) {
            unsigned short hh, ll;
            bf16_split(vb[jj][c], hh, ll);
            sB[0][0][lane + 32 * c][wid + 8 * jj] = __ushort_as_bfloat16(hh);
            sB[0][1][lane + 32 * c][wid + 8 * jj] = __ushort_as_bfloat16(ll);
        }
    __syncthreads();

    const int kb = tig * 2;
    for (int kt = 0; kt < NST; kt++) {
        const int buf = kt & 1;
        if (kt + 1 < NST) {
            const int k0 = (kt + 1) * BKS;
            #pragma unroll
            for (int i = 0; i < 2; i++)
                va[i] = *(const float4*)(A + (size_t)(row0 + ar0 + i * 64) * GK + k0 + ac0);
            #pragma unroll
            for (int jj = 0; jj < 2; jj++)
                #pragma unroll
                for (int c = 0; c < 4; c++)
                    vb[jj][c] = Bp[(size_t)(k0 + wid + 8 * jj) * N + col0 + lane + 32 * c];
        }

        uint32_t Ah[4][4], Al[4][4];
        #pragma unroll
        for (int mi = 0; mi < 4; mi++) {
            const int r0 = wm * 64 + mi * 16 + gid;
            Ah[mi][0] = *(const uint32_t*)&sA[buf][0][r0][kb];
            Ah[mi][1] = *(const uint32_t*)&sA[buf][0][r0 + 8][kb];
            Ah[mi][2] = *(const uint32_t*)&sA[buf][0][r0][kb + 8];
            Ah[mi][3] = *(const uint32_t*)&sA[buf][0][r0 + 8][kb + 8];
            Al[mi][0] = *(const uint32_t*)&sA[buf][1][r0][kb];
            Al[mi][1] = *(const uint32_t*)&sA[buf][1][r0 + 8][kb];
            Al[mi][2] = *(const uint32_t*)&sA[buf][1][r0][kb + 8];
            Al[mi][3] = *(const uint32_t*)&sA[buf][1][r0 + 8][kb + 8];
        }
        uint32_t Bh[4][2], Bl[4][2];
        #pragma unroll
        for (int ng = 0; ng < 4; ng++) {
            const int nr = wn * 32 + ng * 8 + gid;
            Bh[ng][0] = *(const uint32_t*)&sB[buf][0][nr][kb];
            Bh[ng][1] = *(const uint32_t*)&sB[buf][0][nr][kb + 8];
            Bl[ng][0] = *(const uint32_t*)&sB[buf][1][nr][kb];
            Bl[ng][1] = *(const uint32_t*)&sB[buf][1][nr][kb + 8];
        }
        #pragma unroll
        for (int mi = 0; mi < 4; mi++)
            #pragma unroll
            for (int ng = 0; ng < 4; ng++) {
                MMA_BF16(d[mi][ng], Ah[mi], Bh[ng][0], Bh[ng][1]);
                MMA_BF16(d[mi][ng], Ah[mi], Bl[ng][0], Bl[ng][1]);
                MMA_BF16(d[mi][ng], Al[mi], Bh[ng][0], Bh[ng][1]);
            }

        if (kt + 1 < NST) {
            const int nb = buf ^ 1;
            #pragma unroll
            for (int i = 0; i < 2; i++) {
                const int ra = ar0 + i * 64;
                const float xs[4] = {va[i].x, va[i].y, va[i].z, va[i].w};
                #pragma unroll
                for (int j = 0; j < 2; j++) {
                    uint32_t hi, lo;
                    split2(xs[2 * j + 0], xs[2 * j + 1], hi, lo);
                    *(uint32_t*)&sA[nb][0][ra][ac0 + 2 * j] = hi;
                    *(uint32_t*)&sA[nb][1][ra][ac0 + 2 * j] = lo;
                }
            }
            #pragma unroll
            for (int jj = 0; jj < 2; jj++)
                #pragma unroll
                for (int c = 0; c < 4; c++) {
                    unsigned short hh, ll;
                    bf16_split(vb[jj][c], hh, ll);
                    sB[nb][0][lane + 32 * c][wid + 8 * jj] = __ushort_as_bfloat16(hh);
                    sB[nb][1][lane + 32 * c][wid + 8 * jj] = __ushort_as_bfloat16(ll);
                }
        }
        __syncthreads();
    }

    // ---------------- epilogue ----------------
    #pragma unroll
    for (int mi = 0; mi < 4; mi++)
        #pragma unroll
        for (int ng = 0; ng < 4; ng++) {
            const int n = col0 + wn * 32 + ng * 8 + tig * 2;
            #pragma unroll
            for (int h = 0; h < 2; h++) {
                const int m = row0 + wm * 64 + mi * 16 + gid + h * 8;
                float2 v;
                v.x = d[mi][ng][h * 2 + 0];
                v.y = d[mi][ng][h * 2 + 1];
                if (MODE == 0) {
                    const int b = m >> 11, t = m & (T_ - 1);
                    const int sidx = n >> 10;
                    const int dmi  = n & (D_MODEL - 1);
                    const int hh = dmi >> 6, dk = dmi & (DKH - 1);
                    const int bh = (b << 4) + hh;
                    if (sidx == 0) {            // Q: pre-scale + split
                        uint32_t hi, lo;
                        split2(0.125f * v.x, 0.125f * v.y, hi, lo);
                        const size_t idx = ((size_t)bh * T_ + t) * DKH + dk;
                        *(uint32_t*)&g_qh[idx] = hi;
                        *(uint32_t*)&g_ql[idx] = lo;
                    } else if (sidx == 1) {     // K: split
                        uint32_t hi, lo;
                        split2(v.x, v.y, hi, lo);
                        const size_t idx = ((size_t)bh * T_ + t) * DKH + dk;
                        *(uint32_t*)&g_kh[idx] = hi;
                        *(uint32_t*)&g_kl[idx] = lo;
                    } else {                    // V: split + transpose to [dk][t]
                        unsigned short h0, l0, h1, l1;
                        bf16_split(v.x, h0, l0);
                        bf16_split(v.y, h1, l1);
                        const size_t i0 = ((size_t)bh * DKH + dk) * T_ + t;
                        g_vh[i0] = __ushort_as_bfloat16(h0);
                        g_vl[i0] = __ushort_as_bfloat16(l0);
                        g_vh[i0 + T_] = __ushort_as_bfloat16(h1);
                        g_vl[i0 + T_] = __ushort_as_bfloat16(l1);
                    }
                } else {
                    *(float2*)(Cp + (size_t)m * N + n) = v;
                }
            }
        }
}

// ===================== bf16 HMMA causal flash attention ====================
// 128 q-rows/CTA, 8 warps x 16 rows, 64-key tiles. Inputs are pre-split bf16
// (Q pre-scaled, V pre-transposed) -> hot loop is pure uint4 LDG + STS.
#define VST 72

__global__ __launch_bounds__(256)
void attn_mma()
{
    __shared__ __align__(16) __nv_bfloat16 sKh[64][VST], sKl[64][VST];
    __shared__ __align__(16) __nv_bfloat16 sVh[64][VST], sVl[64][VST];

    const int bh  = blockIdx.y;
    const int q0  = blockIdx.x * 128;
    const int tid = threadIdx.x;
    const int wid = tid >> 5;
    const int lane = tid & 31;
    const int gid = lane >> 2;
    const int tig = lane & 3;

    const __nv_bfloat16* Qh_g = g_qh + ((size_t)bh * T_ + q0) * DKH;
    const __nv_bfloat16* Ql_g = g_ql + ((size_t)bh * T_ + q0) * DKH;
    const __nv_bfloat16* Kh_g = g_kh + (size_t)bh * T_ * DKH;
    const __nv_bfloat16* Kl_g = g_kl + (size_t)bh * T_ * DKH;
    const __nv_bfloat16* Vh_g = g_vh + (size_t)bh * DKH * T_;
    const __nv_bfloat16* Vl_g = g_vl + (size_t)bh * DKH * T_;
    const float LOG2E = 1.4426950408889634f;

    // thread's tile-copy slot: row r8 (0..63), 8-elem chunk dc
    const int r8 = tid >> 3, dc = (tid & 7) * 8;

    // ---- Q fragments (staged through sKh/sKl in two 64-row passes) ----
    uint32_t Qh[4][4], Ql[4][4];
    #pragma unroll
    for (int pass = 0; pass < 2; pass++) {
        #pragma unroll
        for (int i = 0; i < 2; i++) {
            const int r = r8 + ((i & 1) << 5);   // rows r8 and r8+32? no: 2 iters cover 64 rows
            // 256 threads * 2 iters = 512 chunks = 64 rows x 8 chunks
            const int c = tid + i * 256;
            const int rr = c >> 3, cc = (c & 7) * 8;
            *(uint4*)&sKh[rr][cc] = *(const uint4*)(Qh_g + (size_t)(pass * 64 + rr) * DKH + cc);
            *(uint4*)&sKl[rr][cc] = *(const uint4*)(Ql_g + (size_t)(pass * 64 + rr) * DKH + cc);
            (void)r;
        }
        __syncthreads();
        if ((wid >> 2) == pass) {
            const int rb = (wid & 3) * 16 + gid;
            #pragma unroll
            for (int ks = 0; ks < 4; ks++) {
                const int kb = ks * 16 + tig * 2;
                Qh[ks][0] = *(const uint32_t*)&sKh[rb][kb];
                Qh[ks][1] = *(const uint32_t*)&sKh[rb + 8][kb];
                Qh[ks][2] = *(const uint32_t*)&sKh[rb][kb + 8];
                Qh[ks][3] = *(const uint32_t*)&sKh[rb + 8][kb + 8];
                Ql[ks][0] = *(const uint32_t*)&sKl[rb][kb];
                Ql[ks][1] = *(const uint32_t*)&sKl[rb + 8][kb];
                Ql[ks][2] = *(const uint32_t*)&sKl[rb][kb + 8];
                Ql[ks][3] = *(const uint32_t*)&sKl[rb + 8][kb + 8];
            }
        }
        __syncthreads();
    }

    float O[8][4];
    #pragma unroll
    for (int i = 0; i < 8; i++)
        #pragma unroll
        for (int e = 0; e < 4; e++) O[i][e] = 0.f;
    float mr[2] = {-1e30f, -1e30f}, lr[2] = {0.f, 0.f};

    const int qA = q0 + wid * 16 + gid;
    const int ntiles = (q0 >> 6) + 2;

    for (int t = 0; t < ntiles; t++) {
        const int k0 = t * 64;
        // global loads first (in flight across the barrier)
        uint4 kh[2], kl[2], vh[2], vl[2];
        #pragma unroll
        for (int i = 0; i < 2; i++) {
            const int c = tid + i * 256;
            const int rr = c >> 3, cc = (c & 7) * 8;
            kh[i] = *(const uint4*)(Kh_g + (size_t)(k0 + rr) * DKH + cc);
            kl[i] = *(const uint4*)(Kl_g + (size_t)(k0 + rr) * DKH + cc);
            vh[i] = *(const uint4*)(Vh_g + (size_t)rr * T_ + k0 + cc);   // rr = dk
            vl[i] = *(const uint4*)(Vl_g + (size_t)rr * T_ + k0 + cc);
        }
        __syncthreads();   // prev tile's compute done
        #pragma unroll
        for (int i = 0; i < 2; i++) {
            const int c = tid + i * 256;
            const int rr = c >> 3, cc = (c & 7) * 8;
            *(uint4*)&sKh[rr][cc] = kh[i];
            *(uint4*)&sKl[rr][cc] = kl[i];
            *(uint4*)&sVh[rr][cc] = vh[i];
            *(uint4*)&sVl[rr][cc] = vl[i];
        }
        __syncthreads();

        if (k0 <= q0 + wid * 16 + 15) {
            // ---- S = (Q*scale) @ K^T ----
            float S[8][4];
            #pragma unroll
            for (int i = 0; i < 8; i++)
                #pragma unroll
                for (int e = 0; e < 4; e++) S[i][e] = 0.f;
            #pragma unroll
            for (int ks = 0; ks < 4; ks++) {
                const int kb = ks * 16 + tig * 2;
                #pragma unroll
                for (int ng = 0; ng < 8; ng++) {
                    const int nr = ng * 8 + gid;
                    uint32_t bh0 = *(const uint32_t*)&sKh[nr][kb];
                    uint32_t bh1 = *(const uint32_t*)&sKh[nr][kb + 8];
                    uint32_t bl0 = *(const uint32_t*)&sKl[nr][kb];
                    uint32_t bl1 = *(const uint32_t*)&sKl[nr][kb + 8];
                    MMA_BF16(S[ng], Qh[ks], bh0, bh1);
                    MMA_BF16(S[ng], Qh[ks], bl0, bl1);
                    MMA_BF16(S[ng], Ql[ks], bh0, bh1);
                }
            }
            // ---- causal mask ----
            if (k0 + 63 > q0 + wid * 16) {
                #pragma unroll
                for (int ng = 0; ng < 8; ng++)
                    #pragma unroll
                    for (int e = 0; e < 4; e++) {
                        const int key = k0 + ng * 8 + tig * 2 + (e & 1);
                        const int q   = qA + (e >> 1) * 8;
                        if (key > q) S[ng][e] = -1e30f;
                    }
            }
            // ---- online softmax ----
            #pragma unroll
            for (int h = 0; h < 2; h++) {
                float mt = -1e30f;
                #pragma unroll
                for (int ng = 0; ng < 8; ng++)
                    mt = fmaxf(mt, fmaxf(S[ng][2 * h], S[ng][2 * h + 1]));
                mt = fmaxf(mt, __shfl_xor_sync(0xffffffff, mt, 1));
                mt = fmaxf(mt, __shfl_xor_sync(0xffffffff, mt, 2));
                const float mn = fmaxf(mr[h], mt);
                const float alpha = exp2f((mr[h] - mn) * LOG2E);
                float rs = 0.f;
                #pragma unroll
                for (int ng = 0; ng < 8; ng++) {
                    float p0 = exp2f((S[ng][2 * h] - mn) * LOG2E);
                    float p1 = exp2f((S[ng][2 * h + 1] - mn) * LOG2E);
                    S[ng][2 * h] = p0;
                    S[ng][2 * h + 1] = p1;
                    rs += p0 + p1;
                }
                rs += __shfl_xor_sync(0xffffffff, rs, 1);
                rs += __shfl_xor_sync(0xffffffff, rs, 2);
                lr[h] = lr[h] * alpha + rs;
                mr[h] = mn;
                #pragma unroll
                for (int ng = 0; ng < 8; ng++) {
                    O[ng][2 * h] *= alpha;
                    O[ng][2 * h + 1] *= alpha;
                }
            }
            // ---- O += P @ V ----
            #pragma unroll
            for (int ks = 0; ks < 4; ks++) {
                uint32_t Ph[4], Pl[4];
                split2(S[2 * ks][0],     S[2 * ks][1],     Ph[0], Pl[0]);
                split2(S[2 * ks][2],     S[2 * ks][3],     Ph[1], Pl[1]);
                split2(S[2 * ks + 1][0], S[2 * ks + 1][1], Ph[2], Pl[2]);
                split2(S[2 * ks + 1][2], S[2 * ks + 1][3], Ph[3], Pl[3]);
                const int kb = ks * 16 + tig * 2;
                #pragma unroll
                for (int ng = 0; ng < 8; ng++) {
                    const int nr = ng * 8 + gid;
                    uint32_t vh0 = *(const uint32_t*)&sVh[nr][kb];
                    uint32_t vh1 = *(const uint32_t*)&sVh[nr][kb + 8];
                    uint32_t vl0 = *(const uint32_t*)&sVl[nr][kb];
                    uint32_t vl1 = *(const uint32_t*)&sVl[nr][kb + 8];
                    MMA_BF16(O[ng], Ph, vh0, vh1);
                    MMA_BF16(O[ng], Ph, vl0, vl1);
                    MMA_BF16(O[ng], Pl, vh0, vh1);
                }
            }
        }
    }

    // ---- epilogue: normalize + write (B,T,D) ----
    const int b = bh >> 4, h = bh & 15;
    #pragma unroll
    for (int hh = 0; hh < 2; hh++) {
        const float inv = 1.f / lr[hh];
        const int q = qA + hh * 8;
        float* og = g_attn + ((size_t)(b * T_ + q)) * D_MODEL + h * DKH;
        #pragma unroll
        for (int ng = 0; ng < 8; ng++) {
            float2 v;
            v.x = O[ng][2 * hh] * inv;
            v.y = O[ng][2 * hh + 1] * inv;
            *(float2*)(og + ng * 8 + tig * 2) = v;
        }
    }
}

// ---------------------------------------------------------------------------
extern "C" void kernel_launch(void* const* d_in, const int* in_sizes, int n_in,
                              void* d_out, int out_size)
{
    const float* x     = (const float*)d_in[0];
    const float* w_qkv = (const float*)d_in[1];
    const float* w_out = (const float*)d_in[2];
    float* out = (float*)d_out;

    gemm_mma<0><<<dim3(N_QKV / 128, M_TOT / 128), 256>>>(x, w_qkv, nullptr, N_QKV);
    attn_mma<<<dim3(T_ / 128, B_ * N_HEADS), 256>>>();
    gemm_mma<1><<<dim3(D_MODEL / 128, M_TOT / 128), 256>>>(nullptr, w_out, out, D_MODEL);
}